// round 1
// baseline (speedup 1.0000x reference)
#include <cuda_runtime.h>
#include <math.h>

// Problem constants
#define BB  4
#define SS  2048
#define DD  1024
#define HH  16
#define DKK 64
#define MM  (BB * SS)          // 8192 rows

// ---------------------------------------------------------------------------
// Scratch (no allocations allowed -> __device__ globals)
// ---------------------------------------------------------------------------
__device__ float g_q[MM * DD];
__device__ float g_k[MM * DD];
__device__ float g_v[MM * DD];
__device__ float g_ctx[MM * DD];

// ---------------------------------------------------------------------------
// SGEMM + bias: C[M,N] = A[M,K] @ B[K,N] + bias[N]
// 128x128 tile, K-tile 16, 256 threads, 8x8 micro-tile per thread.
// Assumes M%128==0, N%128==0, K%16==0 (true for all calls here).
// ---------------------------------------------------------------------------
__global__ __launch_bounds__(256) void sgemm_bias_kernel(
    const float* __restrict__ A, const float* __restrict__ B,
    const float* __restrict__ bias, float* __restrict__ C,
    int M, int N, int K)
{
    __shared__ float As[16][128];   // As[kk][m] (transposed on store)
    __shared__ float Bs[16][128];   // Bs[kk][n]

    const int tid = threadIdx.x;
    const int tx = tid & 15;        // 0..15 -> n
    const int ty = tid >> 4;        // 0..15 -> m
    const int row0 = blockIdx.y * 128;
    const int col0 = blockIdx.x * 128;

    float acc[8][8];
    #pragma unroll
    for (int i = 0; i < 8; i++)
        #pragma unroll
        for (int j = 0; j < 8; j++) acc[i][j] = 0.0f;

    const int aRow = tid >> 2;          // 0..63
    const int aC4  = (tid & 3) * 4;     // 0,4,8,12

    const int bk0 = tid >> 5;           // 0..7
    const int bn0 = (tid & 31) * 4;     // 0..124
    const int bk1 = bk0 + 8;

    for (int k0 = 0; k0 < K; k0 += 16) {
        float4 a0 = *(const float4*)&A[(size_t)(row0 + aRow)      * K + k0 + aC4];
        float4 a1 = *(const float4*)&A[(size_t)(row0 + aRow + 64) * K + k0 + aC4];
        float4 b0 = *(const float4*)&B[(size_t)(k0 + bk0) * N + col0 + bn0];
        float4 b1 = *(const float4*)&B[(size_t)(k0 + bk1) * N + col0 + bn0];

        __syncthreads();
        As[aC4 + 0][aRow] = a0.x;
        As[aC4 + 1][aRow] = a0.y;
        As[aC4 + 2][aRow] = a0.z;
        As[aC4 + 3][aRow] = a0.w;
        As[aC4 + 0][aRow + 64] = a1.x;
        As[aC4 + 1][aRow + 64] = a1.y;
        As[aC4 + 2][aRow + 64] = a1.z;
        As[aC4 + 3][aRow + 64] = a1.w;
        *(float4*)&Bs[bk0][bn0] = b0;
        *(float4*)&Bs[bk1][bn0] = b1;
        __syncthreads();

        #pragma unroll
        for (int kk = 0; kk < 16; kk++) {
            float4 af0 = *(float4*)&As[kk][ty * 8];
            float4 af1 = *(float4*)&As[kk][ty * 8 + 4];
            float4 bf0 = *(float4*)&Bs[kk][tx * 8];
            float4 bf1 = *(float4*)&Bs[kk][tx * 8 + 4];
            float a[8] = {af0.x, af0.y, af0.z, af0.w, af1.x, af1.y, af1.z, af1.w};
            float b[8] = {bf0.x, bf0.y, bf0.z, bf0.w, bf1.x, bf1.y, bf1.z, bf1.w};
            #pragma unroll
            for (int i = 0; i < 8; i++)
                #pragma unroll
                for (int j = 0; j < 8; j++)
                    acc[i][j] += a[i] * b[j];
        }
    }

    float4 bia0 = *(const float4*)&bias[col0 + tx * 8];
    float4 bia1 = *(const float4*)&bias[col0 + tx * 8 + 4];
    #pragma unroll
    for (int i = 0; i < 8; i++) {
        size_t r = (size_t)(row0 + ty * 8 + i) * N + col0 + tx * 8;
        float4 o0 = {acc[i][0] + bia0.x, acc[i][1] + bia0.y,
                     acc[i][2] + bia0.z, acc[i][3] + bia0.w};
        float4 o1 = {acc[i][4] + bia1.x, acc[i][5] + bia1.y,
                     acc[i][6] + bia1.z, acc[i][7] + bia1.w};
        *(float4*)&C[r]     = o0;
        *(float4*)&C[r + 4] = o1;
    }
}

// ---------------------------------------------------------------------------
// Flash attention fp32: per (b,h), online-softmax over S=2048, DK=64.
// BM=BN=64, 256 threads (16x16), 4x4 micro-tiles for both GEMMs.
// Q/K/V laid out as [B,S,H*DK] (natural GEMM output layout).
// ---------------------------------------------------------------------------
#define FA_PAD 65   // padded row stride to avoid 32-way bank conflicts

__global__ __launch_bounds__(256) void flash_kernel(
    const float* __restrict__ Q, const float* __restrict__ K,
    const float* __restrict__ V, float* __restrict__ O)
{
    extern __shared__ float sm[];
    float* Qs = sm;                    // 64 * 65
    float* Ks = sm + 64 * FA_PAD;      // 64 * 65
    float* Ps = sm + 2 * 64 * FA_PAD;  // 64 * 65
    float* Vs = sm + 3 * 64 * FA_PAD;  // 64 * 64 (unpadded: float4 reads)

    const int tid = threadIdx.x;
    const int tx = tid & 15;           // -> kv cols (gemm1) / head-dim cols (gemm2)
    const int ty = tid >> 4;           // -> query rows
    const int bh = blockIdx.y;
    const int b = bh >> 4;             // / HH
    const int h = bh & 15;
    const int q0 = blockIdx.x * 64;

    const size_t base_q  = ((size_t)(b * SS + q0)) * DD + h * DKK;
    const size_t base_kv0 = ((size_t)(b * SS)) * DD + h * DKK;

    // Load Q tile (64 x 64)
    #pragma unroll
    for (int it = 0; it < 4; it++) {
        int idx = tid + it * 256;
        int row = idx >> 4;
        int c4  = (idx & 15) * 4;
        float4 qv = *(const float4*)&Q[base_q + (size_t)row * DD + c4];
        Qs[row * FA_PAD + c4 + 0] = qv.x;
        Qs[row * FA_PAD + c4 + 1] = qv.y;
        Qs[row * FA_PAD + c4 + 2] = qv.z;
        Qs[row * FA_PAD + c4 + 3] = qv.w;
    }

    float mrow[4], lrow[4], acc[4][4];
    #pragma unroll
    for (int r = 0; r < 4; r++) {
        mrow[r] = -1e30f;
        lrow[r] = 0.0f;
        #pragma unroll
        for (int c = 0; c < 4; c++) acc[r][c] = 0.0f;
    }

    for (int kt = 0; kt < SS; kt += 64) {
        __syncthreads();   // previous iteration fully done with Ks/Vs/Ps
        const size_t base_kv = base_kv0 + (size_t)kt * DD;
        #pragma unroll
        for (int it = 0; it < 4; it++) {
            int idx = tid + it * 256;
            int row = idx >> 4;
            int c4  = (idx & 15) * 4;
            float4 kv = *(const float4*)&K[base_kv + (size_t)row * DD + c4];
            Ks[row * FA_PAD + c4 + 0] = kv.x;
            Ks[row * FA_PAD + c4 + 1] = kv.y;
            Ks[row * FA_PAD + c4 + 2] = kv.z;
            Ks[row * FA_PAD + c4 + 3] = kv.w;
            float4 vv = *(const float4*)&V[base_kv + (size_t)row * DD + c4];
            *(float4*)&Vs[row * 64 + c4] = vv;
        }
        __syncthreads();

        // GEMM1: s[r][c] = sum_d Q[qrow][d] * K[kcol][d]
        float s[4][4];
        #pragma unroll
        for (int r = 0; r < 4; r++)
            #pragma unroll
            for (int c = 0; c < 4; c++) s[r][c] = 0.0f;

        #pragma unroll 8
        for (int d = 0; d < 64; d++) {
            float qf[4], kf[4];
            #pragma unroll
            for (int r = 0; r < 4; r++) qf[r] = Qs[(ty * 4 + r) * FA_PAD + d];
            #pragma unroll
            for (int c = 0; c < 4; c++) kf[c] = Ks[(tx * 4 + c) * FA_PAD + d];
            #pragma unroll
            for (int r = 0; r < 4; r++)
                #pragma unroll
                for (int c = 0; c < 4; c++)
                    s[r][c] += qf[r] * kf[c];
        }

        // Online softmax per row (reduce across the 16 tx lanes)
        #pragma unroll
        for (int r = 0; r < 4; r++) {
            #pragma unroll
            for (int c = 0; c < 4; c++) s[r][c] *= 0.125f;   // 1/sqrt(64)
            float mx = fmaxf(fmaxf(s[r][0], s[r][1]), fmaxf(s[r][2], s[r][3]));
            #pragma unroll
            for (int o = 8; o >= 1; o >>= 1)
                mx = fmaxf(mx, __shfl_xor_sync(0xffffffffu, mx, o));
            float mnew = fmaxf(mrow[r], mx);
            float corr = __expf(mrow[r] - mnew);
            float ps = 0.0f;
            #pragma unroll
            for (int c = 0; c < 4; c++) {
                float p = __expf(s[r][c] - mnew);
                s[r][c] = p;
                ps += p;
            }
            #pragma unroll
            for (int o = 8; o >= 1; o >>= 1)
                ps += __shfl_xor_sync(0xffffffffu, ps, o);
            lrow[r] = lrow[r] * corr + ps;
            mrow[r] = mnew;
            #pragma unroll
            for (int c = 0; c < 4; c++) acc[r][c] *= corr;
            #pragma unroll
            for (int c = 0; c < 4; c++)
                Ps[(ty * 4 + r) * FA_PAD + tx * 4 + c] = s[r][c];
        }
        __syncthreads();

        // GEMM2: acc[r][c] += sum_j P[qrow][j] * V[j][dcol]
        #pragma unroll 8
        for (int j = 0; j < 64; j++) {
            float4 vf = *(float4*)&Vs[j * 64 + tx * 4];
            float pf[4];
            #pragma unroll
            for (int r = 0; r < 4; r++) pf[r] = Ps[(ty * 4 + r) * FA_PAD + j];
            #pragma unroll
            for (int r = 0; r < 4; r++) {
                acc[r][0] += pf[r] * vf.x;
                acc[r][1] += pf[r] * vf.y;
                acc[r][2] += pf[r] * vf.z;
                acc[r][3] += pf[r] * vf.w;
            }
        }
    }

    // Epilogue: normalize and store ctx in [B,S,H*DK]
    #pragma unroll
    for (int r = 0; r < 4; r++) {
        float inv = 1.0f / lrow[r];
        size_t o = base_q + (size_t)(ty * 4 + r) * DD + tx * 4;
        float4 ov = {acc[r][0] * inv, acc[r][1] * inv,
                     acc[r][2] * inv, acc[r][3] * inv};
        *(float4*)&O[o] = ov;
    }
}

// ---------------------------------------------------------------------------
// Launch
// ---------------------------------------------------------------------------
extern "C" void kernel_launch(void* const* d_in, const int* in_sizes, int n_in,
                              void* d_out, int out_size)
{
    const float* x  = (const float*)d_in[0];
    const float* wq = (const float*)d_in[1];
    const float* bq = (const float*)d_in[2];
    const float* wk = (const float*)d_in[3];
    const float* bk = (const float*)d_in[4];
    const float* wv = (const float*)d_in[5];
    const float* bv = (const float*)d_in[6];
    const float* wo = (const float*)d_in[7];
    const float* bo = (const float*)d_in[8];
    float* out = (float*)d_out;

    float *q, *k, *v, *ctx;
    cudaGetSymbolAddress((void**)&q,   g_q);
    cudaGetSymbolAddress((void**)&k,   g_k);
    cudaGetSymbolAddress((void**)&v,   g_v);
    cudaGetSymbolAddress((void**)&ctx, g_ctx);

    const int fa_smem = (3 * 64 * FA_PAD + 64 * 64) * sizeof(float);  // 66304 B
    cudaFuncSetAttribute(flash_kernel,
                         cudaFuncAttributeMaxDynamicSharedMemorySize, fa_smem);

    dim3 gemm_grid(DD / 128, MM / 128);   // (8, 64)

    sgemm_bias_kernel<<<gemm_grid, 256>>>(x, wq, bq, q, MM, DD, DD);
    sgemm_bias_kernel<<<gemm_grid, 256>>>(x, wk, bk, k, MM, DD, DD);
    sgemm_bias_kernel<<<gemm_grid, 256>>>(x, wv, bv, v, MM, DD, DD);

    dim3 fa_grid(SS / 64, BB * HH);       // (32, 64)
    flash_kernel<<<fa_grid, 256, fa_smem>>>(q, k, v, ctx);

    sgemm_bias_kernel<<<gemm_grid, 256>>>(ctx, wo, bo, out, MM, DD, DD);
}

// round 6
// speedup vs baseline: 3.1689x; 3.1689x over previous
#include <cuda_runtime.h>
#include <stdint.h>
#include <math.h>

// Problem constants
#define BB  4
#define SS  2048
#define DD  1024
#define HH  16
#define DKK 64
#define MM  (BB * SS)          // 8192 rows

// ---------------------------------------------------------------------------
// Scratch (no allocations allowed -> __device__ globals)
// ---------------------------------------------------------------------------
__device__ float g_q[MM * DD];
__device__ float g_k[MM * DD];
__device__ float g_v[MM * DD];
__device__ float g_ctx[MM * DD];

// ---------------------------------------------------------------------------
// tf32 helpers
// ---------------------------------------------------------------------------
__device__ __forceinline__ float f2tf32(float x) {
    uint32_t r;
    asm("cvt.rna.tf32.f32 %0, %1;" : "=r"(r) : "f"(x));
    return __uint_as_float(r);
}

__device__ __forceinline__ void mma_tf32(
    float& c0, float& c1, float& c2, float& c3,
    uint32_t a0, uint32_t a1, uint32_t a2, uint32_t a3,
    uint32_t b0, uint32_t b1)
{
    asm volatile(
        "mma.sync.aligned.m16n8k8.row.col.f32.tf32.tf32.f32 "
        "{%0,%1,%2,%3}, {%4,%5,%6,%7}, {%8,%9}, {%0,%1,%2,%3};"
        : "+f"(c0), "+f"(c1), "+f"(c2), "+f"(c3)
        : "r"(a0), "r"(a1), "r"(a2), "r"(a3), "r"(b0), "r"(b1));
}

// ---------------------------------------------------------------------------
// tf32 tensor-core GEMM + bias: C[M,N] = A[M,K] @ B[K,N] + bias[N]
// Block tile 128x128, K-tile 32, 256 threads (8 warps), warp tile 64x32.
// As[m][k] stride 36  (frag-load banks = g*4+j : conflict-free)
// Bs[k][n] stride 136 (frag-load banks = j*8+g : conflict-free)
// ---------------------------------------------------------------------------
#define AS_STRIDE 36
#define BS_STRIDE 136

__global__ __launch_bounds__(256) void gemm_tc_kernel(
    const float* __restrict__ A, const float* __restrict__ B,
    const float* __restrict__ bias, float* __restrict__ C,
    int M, int N, int K)
{
    __shared__ float As[128 * AS_STRIDE];
    __shared__ float Bs[32 * BS_STRIDE];

    const int tid  = threadIdx.x;
    const int lane = tid & 31;
    const int wid  = tid >> 5;
    const int g    = lane >> 2;     // groupID 0..7
    const int j    = lane & 3;      // thread-in-group 0..3

    const int warp_m = wid & 1;     // 2 warps along M
    const int warp_n = wid >> 1;    // 4 warps along N
    const int m0 = warp_m * 64;
    const int n0 = warp_n * 32;

    const int row0 = blockIdx.y * 128;
    const int col0 = blockIdx.x * 128;

    // global load indices
    const int ar  = tid >> 3;            // 0..31
    const int ac4 = (tid & 7) * 4;       // 0..28
    const int bk  = tid >> 5;            // 0..7
    const int bc4 = (tid & 31) * 4;      // 0..124

    float acc[4][4][4];
    #pragma unroll
    for (int mt = 0; mt < 4; mt++)
        #pragma unroll
        for (int nt = 0; nt < 4; nt++)
            #pragma unroll
            for (int i = 0; i < 4; i++) acc[mt][nt][i] = 0.0f;

    for (int k0 = 0; k0 < K; k0 += 32) {
        float4 av[4], bv[4];
        #pragma unroll
        for (int p = 0; p < 4; p++) {
            av[p] = *(const float4*)&A[(size_t)(row0 + ar + p * 32) * K + k0 + ac4];
            bv[p] = *(const float4*)&B[(size_t)(k0 + bk + p * 8) * N + col0 + bc4];
        }

        __syncthreads();
        #pragma unroll
        for (int p = 0; p < 4; p++) {
            float* as = &As[(ar + p * 32) * AS_STRIDE + ac4];
            as[0] = f2tf32(av[p].x);
            as[1] = f2tf32(av[p].y);
            as[2] = f2tf32(av[p].z);
            as[3] = f2tf32(av[p].w);
            float4 bt = {f2tf32(bv[p].x), f2tf32(bv[p].y),
                         f2tf32(bv[p].z), f2tf32(bv[p].w)};
            *(float4*)&Bs[(bk + p * 8) * BS_STRIDE + bc4] = bt;
        }
        __syncthreads();

        #pragma unroll
        for (int kk = 0; kk < 32; kk += 8) {
            uint32_t af[4][4], bf[4][2];
            #pragma unroll
            for (int mt = 0; mt < 4; mt++) {
                int r = m0 + mt * 16 + g;
                af[mt][0] = __float_as_uint(As[r * AS_STRIDE + kk + j]);
                af[mt][1] = __float_as_uint(As[(r + 8) * AS_STRIDE + kk + j]);
                af[mt][2] = __float_as_uint(As[r * AS_STRIDE + kk + j + 4]);
                af[mt][3] = __float_as_uint(As[(r + 8) * AS_STRIDE + kk + j + 4]);
            }
            #pragma unroll
            for (int nt = 0; nt < 4; nt++) {
                int c = n0 + nt * 8 + g;
                bf[nt][0] = __float_as_uint(Bs[(kk + j) * BS_STRIDE + c]);
                bf[nt][1] = __float_as_uint(Bs[(kk + j + 4) * BS_STRIDE + c]);
            }
            #pragma unroll
            for (int mt = 0; mt < 4; mt++)
                #pragma unroll
                for (int nt = 0; nt < 4; nt++)
                    mma_tf32(acc[mt][nt][0], acc[mt][nt][1],
                             acc[mt][nt][2], acc[mt][nt][3],
                             af[mt][0], af[mt][1], af[mt][2], af[mt][3],
                             bf[nt][0], bf[nt][1]);
        }
    }

    // Epilogue with bias
    #pragma unroll
    for (int mt = 0; mt < 4; mt++) {
        int r = row0 + m0 + mt * 16 + g;
        #pragma unroll
        for (int nt = 0; nt < 4; nt++) {
            int c = col0 + n0 + nt * 8 + 2 * j;
            float b0 = bias[c], b1 = bias[c + 1];
            float2 o0 = {acc[mt][nt][0] + b0, acc[mt][nt][1] + b1};
            float2 o1 = {acc[mt][nt][2] + b0, acc[mt][nt][3] + b1};
            *(float2*)&C[(size_t)r * N + c]       = o0;
            *(float2*)&C[(size_t)(r + 8) * N + c] = o1;
        }
    }
}

// ---------------------------------------------------------------------------
// Flash attention, tf32 tensor cores.
// Q-tile 128, KV-tile 64, DK=64. 256 threads = 8 warps, each warp owns 16
// query rows. Q fragments live in registers for the whole block.
// Ks/Vs/Ps in SMEM, stride 68 (conflict-free fragment access).
// ---------------------------------------------------------------------------
#define FS 68

__global__ __launch_bounds__(256) void flash_tc_kernel(
    const float* __restrict__ Q, const float* __restrict__ K,
    const float* __restrict__ V, float* __restrict__ O)
{
    extern __shared__ float sm[];
    float* Ks = sm;                 // [64][FS]
    float* Vs = sm + 64 * FS;       // [64][FS]
    float* Ps = sm + 2 * 64 * FS;   // [128][FS]

    const int tid  = threadIdx.x;
    const int lane = tid & 31;
    const int wid  = tid >> 5;
    const int g    = lane >> 2;
    const int j    = lane & 3;
    const int m0   = wid * 16;      // warp's query-row slab within tile

    const int bh = blockIdx.y;
    const int b  = bh >> 4;
    const int h  = bh & 15;
    const int q0 = blockIdx.x * 128;

    const size_t qrow_base = (size_t)(b * SS + q0);
    const size_t kv_base   = (size_t)(b * SS);
    const int    hoff      = h * DKK;

    // Preload Q fragments (16 rows x 64 dims per warp) as tf32 in registers
    uint32_t qf[8][4];
    {
        const float* qp = Q + (qrow_base + m0 + g) * DD + hoff;
        const float* qp8 = qp + 8 * DD;
        #pragma unroll
        for (int kc = 0; kc < 8; kc++) {
            int d = kc * 8 + j;
            qf[kc][0] = __float_as_uint(f2tf32(qp[d]));
            qf[kc][1] = __float_as_uint(f2tf32(qp8[d]));
            qf[kc][2] = __float_as_uint(f2tf32(qp[d + 4]));
            qf[kc][3] = __float_as_uint(f2tf32(qp8[d + 4]));
        }
    }

    float out[8][4];
    #pragma unroll
    for (int nt = 0; nt < 8; nt++)
        #pragma unroll
        for (int i = 0; i < 4; i++) out[nt][i] = 0.0f;
    float mprev0 = -1e30f, mprev1 = -1e30f, l0 = 0.0f, l1 = 0.0f;

    const int ldr  = tid >> 4;        // 0..15
    const int ldc4 = (tid & 15) * 4;  // 0..60

    for (int kt = 0; kt < SS; kt += 64) {
        __syncthreads();
        const float* kp = K + (kv_base + kt) * DD + hoff;
        const float* vp = V + (kv_base + kt) * DD + hoff;
        #pragma unroll
        for (int p = 0; p < 4; p++) {
            int row = ldr + p * 16;
            float4 kv = *(const float4*)&kp[(size_t)row * DD + ldc4];
            float4 vv = *(const float4*)&vp[(size_t)row * DD + ldc4];
            float* ks = &Ks[row * FS + ldc4];
            ks[0] = f2tf32(kv.x); ks[1] = f2tf32(kv.y);
            ks[2] = f2tf32(kv.z); ks[3] = f2tf32(kv.w);
            float4 vt = {f2tf32(vv.x), f2tf32(vv.y), f2tf32(vv.z), f2tf32(vv.w)};
            *(float4*)&Vs[row * FS + ldc4] = vt;
        }
        __syncthreads();

        // S = Q @ K^T  (16 x 64 per warp)
        float s[8][4];
        #pragma unroll
        for (int nt = 0; nt < 8; nt++)
            #pragma unroll
            for (int i = 0; i < 4; i++) s[nt][i] = 0.0f;

        #pragma unroll
        for (int kc = 0; kc < 8; kc++) {
            int d = kc * 8 + j;
            #pragma unroll
            for (int nt = 0; nt < 8; nt++) {
                uint32_t b0 = __float_as_uint(Ks[(nt * 8 + g) * FS + d]);
                uint32_t b1 = __float_as_uint(Ks[(nt * 8 + g) * FS + d + 4]);
                mma_tf32(s[nt][0], s[nt][1], s[nt][2], s[nt][3],
                         qf[kc][0], qf[kc][1], qf[kc][2], qf[kc][3], b0, b1);
            }
        }

        // Online softmax on fragments (rows g and g+8 of the warp slab)
        float mx0 = -1e30f, mx1 = -1e30f;
        #pragma unroll
        for (int nt = 0; nt < 8; nt++) {
            s[nt][0] *= 0.125f; s[nt][1] *= 0.125f;
            s[nt][2] *= 0.125f; s[nt][3] *= 0.125f;
            mx0 = fmaxf(mx0, fmaxf(s[nt][0], s[nt][1]));
            mx1 = fmaxf(mx1, fmaxf(s[nt][2], s[nt][3]));
        }
        mx0 = fmaxf(mx0, __shfl_xor_sync(0xffffffffu, mx0, 1));
        mx0 = fmaxf(mx0, __shfl_xor_sync(0xffffffffu, mx0, 2));
        mx1 = fmaxf(mx1, __shfl_xor_sync(0xffffffffu, mx1, 1));
        mx1 = fmaxf(mx1, __shfl_xor_sync(0xffffffffu, mx1, 2));

        float mn0 = fmaxf(mprev0, mx0);
        float mn1 = fmaxf(mprev1, mx1);
        float corr0 = __expf(mprev0 - mn0);
        float corr1 = __expf(mprev1 - mn1);
        mprev0 = mn0; mprev1 = mn1;

        float sum0 = 0.0f, sum1 = 0.0f;
        float* pr0 = &Ps[(m0 + g) * FS + 2 * j];
        float* pr1 = &Ps[(m0 + g + 8) * FS + 2 * j];
        #pragma unroll
        for (int nt = 0; nt < 8; nt++) {
            float p0 = __expf(s[nt][0] - mn0);
            float p1 = __expf(s[nt][1] - mn0);
            float p2 = __expf(s[nt][2] - mn1);
            float p3 = __expf(s[nt][3] - mn1);
            sum0 += p0 + p1;
            sum1 += p2 + p3;
            float2 w0 = {f2tf32(p0), f2tf32(p1)};
            float2 w1 = {f2tf32(p2), f2tf32(p3)};
            *(float2*)&pr0[nt * 8] = w0;
            *(float2*)&pr1[nt * 8] = w1;
        }
        sum0 += __shfl_xor_sync(0xffffffffu, sum0, 1);
        sum0 += __shfl_xor_sync(0xffffffffu, sum0, 2);
        sum1 += __shfl_xor_sync(0xffffffffu, sum1, 1);
        sum1 += __shfl_xor_sync(0xffffffffu, sum1, 2);
        l0 = l0 * corr0 + sum0;
        l1 = l1 * corr1 + sum1;

        #pragma unroll
        for (int nt = 0; nt < 8; nt++) {
            out[nt][0] *= corr0; out[nt][1] *= corr0;
            out[nt][2] *= corr1; out[nt][3] *= corr1;
        }

        // Make this warp's P stores visible to all its lanes before P@V reads
        __syncwarp();

        // out += P @ V   (P rows are warp-private)
        #pragma unroll
        for (int kc = 0; kc < 8; kc++) {
            int kr = kc * 8;
            uint32_t a0 = __float_as_uint(Ps[(m0 + g) * FS + kr + j]);
            uint32_t a1 = __float_as_uint(Ps[(m0 + g + 8) * FS + kr + j]);
            uint32_t a2 = __float_as_uint(Ps[(m0 + g) * FS + kr + j + 4]);
            uint32_t a3 = __float_as_uint(Ps[(m0 + g + 8) * FS + kr + j + 4]);
            #pragma unroll
            for (int nt = 0; nt < 8; nt++) {
                uint32_t b0 = __float_as_uint(Vs[(kr + j) * FS + nt * 8 + g]);
                uint32_t b1 = __float_as_uint(Vs[(kr + j + 4) * FS + nt * 8 + g]);
                mma_tf32(out[nt][0], out[nt][1], out[nt][2], out[nt][3],
                         a0, a1, a2, a3, b0, b1);
            }
        }
    }

    // Epilogue: normalize, store ctx [B,S,D]
    float inv0 = 1.0f / l0;
    float inv1 = 1.0f / l1;
    float* op0 = O + (qrow_base + m0 + g) * DD + hoff + 2 * j;
    float* op1 = O + (qrow_base + m0 + g + 8) * DD + hoff + 2 * j;
    #pragma unroll
    for (int nt = 0; nt < 8; nt++) {
        float2 o0 = {out[nt][0] * inv0, out[nt][1] * inv0};
        float2 o1 = {out[nt][2] * inv1, out[nt][3] * inv1};
        *(float2*)&op0[nt * 8] = o0;
        *(float2*)&op1[nt * 8] = o1;
    }
}

// ---------------------------------------------------------------------------
// Launch
// ---------------------------------------------------------------------------
extern "C" void kernel_launch(void* const* d_in, const int* in_sizes, int n_in,
                              void* d_out, int out_size)
{
    const float* x  = (const float*)d_in[0];
    const float* wq = (const float*)d_in[1];
    const float* bq = (const float*)d_in[2];
    const float* wk = (const float*)d_in[3];
    const float* bk = (const float*)d_in[4];
    const float* wv = (const float*)d_in[5];
    const float* bv = (const float*)d_in[6];
    const float* wo = (const float*)d_in[7];
    const float* bo = (const float*)d_in[8];
    float* out = (float*)d_out;

    float *q, *k, *v, *ctx;
    cudaGetSymbolAddress((void**)&q,   g_q);
    cudaGetSymbolAddress((void**)&k,   g_k);
    cudaGetSymbolAddress((void**)&v,   g_v);
    cudaGetSymbolAddress((void**)&ctx, g_ctx);

    const int fa_smem = (2 * 64 * FS + 128 * FS) * sizeof(float);  // 69632 B
    cudaFuncSetAttribute(flash_tc_kernel,
                         cudaFuncAttributeMaxDynamicSharedMemorySize, fa_smem);

    dim3 gemm_grid(DD / 128, MM / 128);   // (8, 64)

    gemm_tc_kernel<<<gemm_grid, 256>>>(x, wq, bq, q, MM, DD, DD);
    gemm_tc_kernel<<<gemm_grid, 256>>>(x, wk, bk, k, MM, DD, DD);
    gemm_tc_kernel<<<gemm_grid, 256>>>(x, wv, bv, v, MM, DD, DD);

    dim3 fa_grid(SS / 128, BB * HH);      // (16, 64)
    flash_tc_kernel<<<fa_grid, 256, fa_smem>>>(q, k, v, ctx);

    gemm_tc_kernel<<<gemm_grid, 256>>>(ctx, wo, bo, out, MM, DD, DD);
}

// round 9
// speedup vs baseline: 3.3641x; 1.0616x over previous
#include <cuda_runtime.h>
#include <stdint.h>
#include <math.h>

// Problem constants
#define BB  4
#define SS  2048
#define DD  1024
#define HH  16
#define DKK 64
#define MM  (BB * SS)          // 8192 rows

// ---------------------------------------------------------------------------
// Scratch (no allocations allowed -> __device__ globals)
// ---------------------------------------------------------------------------
__device__ float g_q[MM * DD];
__device__ float g_k[MM * DD];
__device__ float g_v[MM * DD];
__device__ float g_ctx[MM * DD];

// ---------------------------------------------------------------------------
// tf32 helpers
// ---------------------------------------------------------------------------
__device__ __forceinline__ float f2tf32(float x) {
    uint32_t r;
    asm("cvt.rna.tf32.f32 %0, %1;" : "=r"(r) : "f"(x));
    return __uint_as_float(r);
}

__device__ __forceinline__ void mma_tf32(
    float& c0, float& c1, float& c2, float& c3,
    uint32_t a0, uint32_t a1, uint32_t a2, uint32_t a3,
    uint32_t b0, uint32_t b1)
{
    asm volatile(
        "mma.sync.aligned.m16n8k8.row.col.f32.tf32.tf32.f32 "
        "{%0,%1,%2,%3}, {%4,%5,%6,%7}, {%8,%9}, {%0,%1,%2,%3};"
        : "+f"(c0), "+f"(c1), "+f"(c2), "+f"(c3)
        : "r"(a0), "r"(a1), "r"(a2), "r"(a3), "r"(b0), "r"(b1));
}

// Packed position of dim d within its 8-group: pairs (j, j+4) become adjacent.
__device__ __forceinline__ int packpos(int d) {
    return ((d >> 3) << 3) + ((d & 3) << 1) + ((d & 7) >> 2);
}

// ---------------------------------------------------------------------------
// tf32 tensor-core GEMM + bias: C[M,N] = A[M,K] @ B[K,N] + bias[N]
// Block tile 128x128, K-tile 32, 256 threads (8 warps), warp tile 64x32.
// Software prefetch: next k-tile's LDG issued before current mma loop.
// ---------------------------------------------------------------------------
#define AS_STRIDE 36
#define BS_STRIDE 136

__global__ __launch_bounds__(256) void gemm_tc_kernel(
    const float* __restrict__ A, const float* __restrict__ B,
    const float* __restrict__ bias, float* __restrict__ C,
    int M, int N, int K)
{
    __shared__ float As[128 * AS_STRIDE];
    __shared__ float Bs[32 * BS_STRIDE];

    const int tid  = threadIdx.x;
    const int lane = tid & 31;
    const int wid  = tid >> 5;
    const int g    = lane >> 2;     // groupID 0..7
    const int j    = lane & 3;      // thread-in-group 0..3

    const int warp_m = wid & 1;     // 2 warps along M
    const int warp_n = wid >> 1;    // 4 warps along N
    const int m0 = warp_m * 64;
    const int n0 = warp_n * 32;

    const int row0 = blockIdx.y * 128;
    const int col0 = blockIdx.x * 128;

    // global load indices
    const int ar  = tid >> 3;            // 0..31
    const int ac4 = (tid & 7) * 4;       // 0..28
    const int bk  = tid >> 5;            // 0..7
    const int bc4 = (tid & 31) * 4;      // 0..124

    float acc[4][4][4];
    #pragma unroll
    for (int mt = 0; mt < 4; mt++)
        #pragma unroll
        for (int nt = 0; nt < 4; nt++)
            #pragma unroll
            for (int i = 0; i < 4; i++) acc[mt][nt][i] = 0.0f;

    // Prologue: load first k-tile
    float4 av[4], bv[4];
    #pragma unroll
    for (int p = 0; p < 4; p++) {
        av[p] = *(const float4*)&A[(size_t)(row0 + ar + p * 32) * K + ac4];
        bv[p] = *(const float4*)&B[(size_t)(bk + p * 8) * N + col0 + bc4];
    }

    for (int k0 = 0; k0 < K; k0 += 32) {
        __syncthreads();
        #pragma unroll
        for (int p = 0; p < 4; p++) {
            float* as = &As[(ar + p * 32) * AS_STRIDE + ac4];
            as[0] = f2tf32(av[p].x);
            as[1] = f2tf32(av[p].y);
            as[2] = f2tf32(av[p].z);
            as[3] = f2tf32(av[p].w);
            float4 bt = {f2tf32(bv[p].x), f2tf32(bv[p].y),
                         f2tf32(bv[p].z), f2tf32(bv[p].w)};
            *(float4*)&Bs[(bk + p * 8) * BS_STRIDE + bc4] = bt;
        }
        __syncthreads();

        // Prefetch next k-tile (hidden behind the mma loop below)
        if (k0 + 32 < K) {
            const int kn = k0 + 32;
            #pragma unroll
            for (int p = 0; p < 4; p++) {
                av[p] = *(const float4*)&A[(size_t)(row0 + ar + p * 32) * K + kn + ac4];
                bv[p] = *(const float4*)&B[(size_t)(kn + bk + p * 8) * N + col0 + bc4];
            }
        }

        #pragma unroll
        for (int kk = 0; kk < 32; kk += 8) {
            uint32_t af[4][4], bf[4][2];
            #pragma unroll
            for (int mt = 0; mt < 4; mt++) {
                int r = m0 + mt * 16 + g;
                af[mt][0] = __float_as_uint(As[r * AS_STRIDE + kk + j]);
                af[mt][1] = __float_as_uint(As[(r + 8) * AS_STRIDE + kk + j]);
                af[mt][2] = __float_as_uint(As[r * AS_STRIDE + kk + j + 4]);
                af[mt][3] = __float_as_uint(As[(r + 8) * AS_STRIDE + kk + j + 4]);
            }
            #pragma unroll
            for (int nt = 0; nt < 4; nt++) {
                int c = n0 + nt * 8 + g;
                bf[nt][0] = __float_as_uint(Bs[(kk + j) * BS_STRIDE + c]);
                bf[nt][1] = __float_as_uint(Bs[(kk + j + 4) * BS_STRIDE + c]);
            }
            #pragma unroll
            for (int mt = 0; mt < 4; mt++)
                #pragma unroll
                for (int nt = 0; nt < 4; nt++)
                    mma_tf32(acc[mt][nt][0], acc[mt][nt][1],
                             acc[mt][nt][2], acc[mt][nt][3],
                             af[mt][0], af[mt][1], af[mt][2], af[mt][3],
                             bf[nt][0], bf[nt][1]);
        }
    }

    // Epilogue with bias
    #pragma unroll
    for (int mt = 0; mt < 4; mt++) {
        int r = row0 + m0 + mt * 16 + g;
        #pragma unroll
        for (int nt = 0; nt < 4; nt++) {
            int c = col0 + n0 + nt * 8 + 2 * j;
            float b0 = bias[c], b1 = bias[c + 1];
            float2 o0 = {acc[mt][nt][0] + b0, acc[mt][nt][1] + b1};
            float2 o1 = {acc[mt][nt][2] + b0, acc[mt][nt][3] + b1};
            *(float2*)&C[(size_t)r * N + c]       = o0;
            *(float2*)&C[(size_t)(r + 8) * N + c] = o1;
        }
    }
}

// ---------------------------------------------------------------------------
// Flash attention, tf32 tensor cores.
// Q-tile 128, KV-tile 64, DK=64. 256 threads = 8 warps, each warp owns 16
// query rows. Q fragments in registers.
// K and P tiles use a pair-packed layout: within each 8-dim group the mma
// fragment pair (j, j+4) sits at adjacent words -> one LDS.64 per fragment.
// All tiles stride FS=72 (packed float2 loads bank-conflict-free: 4g+j).
// ---------------------------------------------------------------------------
#define FS 72

__global__ __launch_bounds__(256) void flash_tc_kernel(
    const float* __restrict__ Q, const float* __restrict__ K,
    const float* __restrict__ V, float* __restrict__ O)
{
    extern __shared__ float sm[];
    float* Ks = sm;                 // [64][FS]  packed
    float* Vs = sm + 64 * FS;       // [64][FS]  row-major (scalar b-frags)
    float* Ps = sm + 2 * 64 * FS;   // [128][FS] packed

    const int tid  = threadIdx.x;
    const int lane = tid & 31;
    const int wid  = tid >> 5;
    const int g    = lane >> 2;
    const int j    = lane & 3;
    const int m0   = wid * 16;      // warp's query-row slab within tile

    const int bh = blockIdx.y;
    const int b  = bh >> 4;
    const int h  = bh & 15;
    const int q0 = blockIdx.x * 128;

    const size_t qrow_base = (size_t)(b * SS + q0);
    const size_t kv_base   = (size_t)(b * SS);
    const int    hoff      = h * DKK;

    // Preload Q fragments (16 rows x 64 dims per warp) as tf32 in registers
    uint32_t qf[8][4];
    {
        const float* qp = Q + (qrow_base + m0 + g) * DD + hoff;
        const float* qp8 = qp + 8 * DD;
        #pragma unroll
        for (int kc = 0; kc < 8; kc++) {
            int d = kc * 8 + j;
            qf[kc][0] = __float_as_uint(f2tf32(qp[d]));
            qf[kc][1] = __float_as_uint(f2tf32(qp8[d]));
            qf[kc][2] = __float_as_uint(f2tf32(qp[d + 4]));
            qf[kc][3] = __float_as_uint(f2tf32(qp8[d + 4]));
        }
    }

    float out[8][4];
    #pragma unroll
    for (int nt = 0; nt < 8; nt++)
        #pragma unroll
        for (int i = 0; i < 4; i++) out[nt][i] = 0.0f;
    float mprev0 = -1e30f, mprev1 = -1e30f, l0 = 0.0f, l1 = 0.0f;

    const int ldr  = tid >> 4;        // 0..15
    const int ldc4 = (tid & 15) * 4;  // 0..60

    // Packed store offset for the P writeback: value pair (col 2j, 2j+1)
    // lands at (nt*8 + off0, nt*8 + off0 + 2).
    const int off0 = (j & 1) * 4 + (j >> 1);

    for (int kt = 0; kt < SS; kt += 64) {
        __syncthreads();
        const float* kp = K + (kv_base + kt) * DD + hoff;
        const float* vp = V + (kv_base + kt) * DD + hoff;
        #pragma unroll
        for (int p = 0; p < 4; p++) {
            int row = ldr + p * 16;
            float4 kv = *(const float4*)&kp[(size_t)row * DD + ldc4];
            float4 vv = *(const float4*)&vp[(size_t)row * DD + ldc4];
            // K: packed scalar stores
            float kvv[4] = {kv.x, kv.y, kv.z, kv.w};
            #pragma unroll
            for (int i = 0; i < 4; i++)
                Ks[row * FS + packpos(ldc4 + i)] = f2tf32(kvv[i]);
            // V: plain row-major float4 store
            float4 vt = {f2tf32(vv.x), f2tf32(vv.y), f2tf32(vv.z), f2tf32(vv.w)};
            *(float4*)&Vs[row * FS + ldc4] = vt;
        }
        __syncthreads();

        // S = Q @ K^T  (16 x 64 per warp); b-fragments via packed LDS.64
        float s[8][4];
        #pragma unroll
        for (int nt = 0; nt < 8; nt++)
            #pragma unroll
            for (int i = 0; i < 4; i++) s[nt][i] = 0.0f;

        #pragma unroll
        for (int kc = 0; kc < 8; kc++) {
            #pragma unroll
            for (int nt = 0; nt < 8; nt++) {
                float2 bb = *(float2*)&Ks[(nt * 8 + g) * FS + kc * 8 + 2 * j];
                mma_tf32(s[nt][0], s[nt][1], s[nt][2], s[nt][3],
                         qf[kc][0], qf[kc][1], qf[kc][2], qf[kc][3],
                         __float_as_uint(bb.x), __float_as_uint(bb.y));
            }
        }

        // Online softmax on fragments (rows g and g+8 of the warp slab)
        float mx0 = -1e30f, mx1 = -1e30f;
        #pragma unroll
        for (int nt = 0; nt < 8; nt++) {
            s[nt][0] *= 0.125f; s[nt][1] *= 0.125f;
            s[nt][2] *= 0.125f; s[nt][3] *= 0.125f;
            mx0 = fmaxf(mx0, fmaxf(s[nt][0], s[nt][1]));
            mx1 = fmaxf(mx1, fmaxf(s[nt][2], s[nt][3]));
        }
        mx0 = fmaxf(mx0, __shfl_xor_sync(0xffffffffu, mx0, 1));
        mx0 = fmaxf(mx0, __shfl_xor_sync(0xffffffffu, mx0, 2));
        mx1 = fmaxf(mx1, __shfl_xor_sync(0xffffffffu, mx1, 1));
        mx1 = fmaxf(mx1, __shfl_xor_sync(0xffffffffu, mx1, 2));

        float mn0 = fmaxf(mprev0, mx0);
        float mn1 = fmaxf(mprev1, mx1);
        float corr0 = __expf(mprev0 - mn0);
        float corr1 = __expf(mprev1 - mn1);
        mprev0 = mn0; mprev1 = mn1;

        float sum0 = 0.0f, sum1 = 0.0f;
        float* prow0 = &Ps[(m0 + g) * FS];
        float* prow1 = &Ps[(m0 + g + 8) * FS];
        #pragma unroll
        for (int nt = 0; nt < 8; nt++) {
            float p0 = __expf(s[nt][0] - mn0);
            float p1 = __expf(s[nt][1] - mn0);
            float p2 = __expf(s[nt][2] - mn1);
            float p3 = __expf(s[nt][3] - mn1);
            sum0 += p0 + p1;
            sum1 += p2 + p3;
            prow0[nt * 8 + off0]     = f2tf32(p0);
            prow0[nt * 8 + off0 + 2] = f2tf32(p1);
            prow1[nt * 8 + off0]     = f2tf32(p2);
            prow1[nt * 8 + off0 + 2] = f2tf32(p3);
        }
        sum0 += __shfl_xor_sync(0xffffffffu, sum0, 1);
        sum0 += __shfl_xor_sync(0xffffffffu, sum0, 2);
        sum1 += __shfl_xor_sync(0xffffffffu, sum1, 1);
        sum1 += __shfl_xor_sync(0xffffffffu, sum1, 2);
        l0 = l0 * corr0 + sum0;
        l1 = l1 * corr1 + sum1;

        #pragma unroll
        for (int nt = 0; nt < 8; nt++) {
            out[nt][0] *= corr0; out[nt][1] *= corr0;
            out[nt][2] *= corr1; out[nt][3] *= corr1;
        }

        // Make this warp's P stores visible to all its lanes before P@V reads
        __syncwarp();

        // out += P @ V   (a-fragments via packed LDS.64; V scalar, conflict-free)
        #pragma unroll
        for (int kc = 0; kc < 8; kc++) {
            int kr = kc * 8;
            float2 pa0 = *(float2*)&prow0[kr + 2 * j];   // (a0, a2)
            float2 pa1 = *(float2*)&prow1[kr + 2 * j];   // (a1, a3)
            uint32_t a0 = __float_as_uint(pa0.x);
            uint32_t a1 = __float_as_uint(pa1.x);
            uint32_t a2 = __float_as_uint(pa0.y);
            uint32_t a3 = __float_as_uint(pa1.y);
            #pragma unroll
            for (int nt = 0; nt < 8; nt++) {
                uint32_t b0 = __float_as_uint(Vs[(kr + j) * FS + nt * 8 + g]);
                uint32_t b1 = __float_as_uint(Vs[(kr + j + 4) * FS + nt * 8 + g]);
                mma_tf32(out[nt][0], out[nt][1], out[nt][2], out[nt][3],
                         a0, a1, a2, a3, b0, b1);
            }
        }
    }

    // Epilogue: normalize, store ctx [B,S,D]
    float inv0 = 1.0f / l0;
    float inv1 = 1.0f / l1;
    float* op0 = O + (qrow_base + m0 + g) * DD + hoff + 2 * j;
    float* op1 = O + (qrow_base + m0 + g + 8) * DD + hoff + 2 * j;
    #pragma unroll
    for (int nt = 0; nt < 8; nt++) {
        float2 o0 = {out[nt][0] * inv0, out[nt][1] * inv0};
        float2 o1 = {out[nt][2] * inv1, out[nt][3] * inv1};
        *(float2*)&op0[nt * 8] = o0;
        *(float2*)&op1[nt * 8] = o1;
    }
}

// ---------------------------------------------------------------------------
// Launch
// ---------------------------------------------------------------------------
extern "C" void kernel_launch(void* const* d_in, const int* in_sizes, int n_in,
                              void* d_out, int out_size)
{
    const float* x  = (const float*)d_in[0];
    const float* wq = (const float*)d_in[1];
    const float* bq = (const float*)d_in[2];
    const float* wk = (const float*)d_in[3];
    const float* bk = (const float*)d_in[4];
    const float* wv = (const float*)d_in[5];
    const float* bv = (const float*)d_in[6];
    const float* wo = (const float*)d_in[7];
    const float* bo = (const float*)d_in[8];
    float* out = (float*)d_out;

    float *q, *k, *v, *ctx;
    cudaGetSymbolAddress((void**)&q,   g_q);
    cudaGetSymbolAddress((void**)&k,   g_k);
    cudaGetSymbolAddress((void**)&v,   g_v);
    cudaGetSymbolAddress((void**)&ctx, g_ctx);

    const int fa_smem = (2 * 64 * FS + 128 * FS) * sizeof(float);  // 73728 B
    cudaFuncSetAttribute(flash_tc_kernel,
                         cudaFuncAttributeMaxDynamicSharedMemorySize, fa_smem);

    dim3 gemm_grid(DD / 128, MM / 128);   // (8, 64)

    gemm_tc_kernel<<<gemm_grid, 256>>>(x, wq, bq, q, MM, DD, DD);
    gemm_tc_kernel<<<gemm_grid, 256>>>(x, wk, bk, k, MM, DD, DD);
    gemm_tc_kernel<<<gemm_grid, 256>>>(x, wv, bv, v, MM, DD, DD);

    dim3 fa_grid(SS / 128, BB * HH);      // (16, 64)
    flash_tc_kernel<<<fa_grid, 256, fa_smem>>>(q, k, v, ctx);

    gemm_tc_kernel<<<gemm_grid, 256>>>(ctx, wo, bo, out, MM, DD, DD);
}

// round 10
// speedup vs baseline: 5.5555x; 1.6514x over previous
#include <cuda_runtime.h>
#include <cuda_fp16.h>
#include <stdint.h>
#include <math.h>

// Problem constants
#define BB  4
#define SS  2048
#define DD  1024
#define HH  16
#define DKK 64
#define MM  (BB * SS)          // 8192 rows

// ---------------------------------------------------------------------------
// Scratch (no allocations allowed -> __device__ globals)
// ---------------------------------------------------------------------------
__device__ float g_q[MM * DD];
__device__ float g_k[MM * DD];
__device__ float g_v[MM * DD];
__device__ float g_ctx[MM * DD];

// ---------------------------------------------------------------------------
// fp16 helpers
// ---------------------------------------------------------------------------
__device__ __forceinline__ uint32_t pack2(float lo, float hi) {
    __half2 h = __floats2half2_rn(lo, hi);
    return *reinterpret_cast<uint32_t*>(&h);
}

// m16n8k16 fp16 mma, fp32 accumulate, row.col
__device__ __forceinline__ void mma_f16(
    float& c0, float& c1, float& c2, float& c3,
    uint32_t a0, uint32_t a1, uint32_t a2, uint32_t a3,
    uint32_t b0, uint32_t b1)
{
    asm volatile(
        "mma.sync.aligned.m16n8k16.row.col.f32.f16.f16.f32 "
        "{%0,%1,%2,%3}, {%4,%5,%6,%7}, {%8,%9}, {%0,%1,%2,%3};"
        : "+f"(c0), "+f"(c1), "+f"(c2), "+f"(c3)
        : "r"(a0), "r"(a1), "r"(a2), "r"(a3), "r"(b0), "r"(b1));
}

// ---------------------------------------------------------------------------
// fp16 tensor-core GEMM + bias: C[M,N] = A[M,K] @ B[K,N] + bias[N]
// Block tile 128x128, K-tile 32, 256 threads (8 warps), warp tile 64x32.
// As: half [128][40]  (row-major, k-pairs contiguous; frag banks 20g+j: CF)
// Bs: uint32(half2) [16][132]: Bs[k/2][n] = {B[k][n], B[k+1][n]} (banks 4j+g: CF)
// Software prefetch of next k-tile.
// ---------------------------------------------------------------------------
#define GA_STRIDE 40    // halfs
#define GB_STRIDE 132   // half2 words

__global__ __launch_bounds__(256) void gemm_tc_kernel(
    const float* __restrict__ A, const float* __restrict__ B,
    const float* __restrict__ bias, float* __restrict__ C,
    int M, int N, int K)
{
    __shared__ __align__(16) __half As[128 * GA_STRIDE];
    __shared__ __align__(16) uint32_t Bs[16 * GB_STRIDE];

    const int tid  = threadIdx.x;
    const int lane = tid & 31;
    const int wid  = tid >> 5;
    const int g    = lane >> 2;     // groupID 0..7
    const int j    = lane & 3;      // thread-in-group 0..3

    const int warp_m = wid & 1;     // 2 warps along M
    const int warp_n = wid >> 1;    // 4 warps along N
    const int m0 = warp_m * 64;
    const int n0 = warp_n * 32;

    const int row0 = blockIdx.y * 128;
    const int col0 = blockIdx.x * 128;

    // global load indices
    const int ar  = tid >> 3;            // 0..31
    const int ac4 = (tid & 7) * 4;       // 0..28
    const int bkp = tid >> 5;            // 0..7 (k-pair base)
    const int bn0 = (tid & 31) * 4;      // 0..124

    float acc[4][4][4];
    #pragma unroll
    for (int mt = 0; mt < 4; mt++)
        #pragma unroll
        for (int nt = 0; nt < 4; nt++)
            #pragma unroll
            for (int i = 0; i < 4; i++) acc[mt][nt][i] = 0.0f;

    // Prologue: load first k-tile
    float4 av[4], bv0[2], bv1[2];
    #pragma unroll
    for (int p = 0; p < 4; p++)
        av[p] = *(const float4*)&A[(size_t)(row0 + ar + p * 32) * K + ac4];
    #pragma unroll
    for (int p = 0; p < 2; p++) {
        int kp = bkp + p * 8;
        bv0[p] = *(const float4*)&B[(size_t)(2 * kp)     * N + col0 + bn0];
        bv1[p] = *(const float4*)&B[(size_t)(2 * kp + 1) * N + col0 + bn0];
    }

    for (int k0 = 0; k0 < K; k0 += 32) {
        __syncthreads();
        #pragma unroll
        for (int p = 0; p < 4; p++) {
            uint2 hp = make_uint2(pack2(av[p].x, av[p].y), pack2(av[p].z, av[p].w));
            *(uint2*)(As + (ar + p * 32) * GA_STRIDE + ac4) = hp;
        }
        #pragma unroll
        for (int p = 0; p < 2; p++) {
            int kp = bkp + p * 8;
            uint4 hb = make_uint4(pack2(bv0[p].x, bv1[p].x), pack2(bv0[p].y, bv1[p].y),
                                  pack2(bv0[p].z, bv1[p].z), pack2(bv0[p].w, bv1[p].w));
            *(uint4*)(Bs + kp * GB_STRIDE + bn0) = hb;
        }
        __syncthreads();

        // Prefetch next k-tile (hidden behind mma loop)
        if (k0 + 32 < K) {
            const int kn = k0 + 32;
            #pragma unroll
            for (int p = 0; p < 4; p++)
                av[p] = *(const float4*)&A[(size_t)(row0 + ar + p * 32) * K + kn + ac4];
            #pragma unroll
            for (int p = 0; p < 2; p++) {
                int kp = bkp + p * 8;
                bv0[p] = *(const float4*)&B[(size_t)(kn + 2 * kp)     * N + col0 + bn0];
                bv1[p] = *(const float4*)&B[(size_t)(kn + 2 * kp + 1) * N + col0 + bn0];
            }
        }

        #pragma unroll
        for (int kc = 0; kc < 2; kc++) {
            uint32_t af[4][4], bf[4][2];
            #pragma unroll
            for (int mt = 0; mt < 4; mt++) {
                const __half* ap = As + (m0 + mt * 16 + g) * GA_STRIDE + kc * 16 + 2 * j;
                af[mt][0] = *(const uint32_t*)ap;
                af[mt][1] = *(const uint32_t*)(ap + 8 * GA_STRIDE);
                af[mt][2] = *(const uint32_t*)(ap + 8);
                af[mt][3] = *(const uint32_t*)(ap + 8 * GA_STRIDE + 8);
            }
            #pragma unroll
            for (int nt = 0; nt < 4; nt++) {
                int c = n0 + nt * 8 + g;
                bf[nt][0] = Bs[(8 * kc + j)     * GB_STRIDE + c];
                bf[nt][1] = Bs[(8 * kc + j + 4) * GB_STRIDE + c];
            }
            #pragma unroll
            for (int mt = 0; mt < 4; mt++)
                #pragma unroll
                for (int nt = 0; nt < 4; nt++)
                    mma_f16(acc[mt][nt][0], acc[mt][nt][1],
                            acc[mt][nt][2], acc[mt][nt][3],
                            af[mt][0], af[mt][1], af[mt][2], af[mt][3],
                            bf[nt][0], bf[nt][1]);
        }
    }

    // Epilogue with bias
    #pragma unroll
    for (int mt = 0; mt < 4; mt++) {
        int r = row0 + m0 + mt * 16 + g;
        #pragma unroll
        for (int nt = 0; nt < 4; nt++) {
            int c = col0 + n0 + nt * 8 + 2 * j;
            float b0 = bias[c], b1 = bias[c + 1];
            float2 o0 = {acc[mt][nt][0] + b0, acc[mt][nt][1] + b1};
            float2 o1 = {acc[mt][nt][2] + b0, acc[mt][nt][3] + b1};
            *(float2*)&C[(size_t)r * N + c]       = o0;
            *(float2*)&C[(size_t)(r + 8) * N + c] = o1;
        }
    }
}

// ---------------------------------------------------------------------------
// Flash attention, fp16 tensor cores (fp32 accumulate & softmax).
// Q-tile 128, KV-tile 64, DK=64. 8 warps x 16 query rows. Q frags in regs.
// Ks: half [64][72] row-major (b-frag pairs naturally adjacent; banks 4g+j CF)
// Vt: half [64][72]: Vt[d] row holds half2{V[2kp][d],V[2kp+1][d]} at word
//     (kp + (d>>3)) & 31  — skew makes both stores and loads conflict-free.
// P tile: never in SMEM — S C-fragments repack directly into PV A-fragments.
// ---------------------------------------------------------------------------
#define KST 72   // halfs per row

__global__ __launch_bounds__(256) void flash_tc_kernel(
    const float* __restrict__ Q, const float* __restrict__ K,
    const float* __restrict__ V, float* __restrict__ O)
{
    __shared__ __align__(16) __half Ks[64 * KST];
    __shared__ __align__(16) __half Vt[64 * KST];

    const int tid  = threadIdx.x;
    const int lane = tid & 31;
    const int wid  = tid >> 5;
    const int g    = lane >> 2;
    const int j    = lane & 3;
    const int m0   = wid * 16;      // warp's query-row slab

    const int bh = blockIdx.y;
    const int b  = bh >> 4;
    const int h  = bh & 15;
    const int q0 = blockIdx.x * 128;

    const size_t qrow_base = (size_t)(b * SS + q0);
    const size_t kv_base   = (size_t)(b * SS);
    const int    hoff      = h * DKK;

    // Preload Q fragments (16 rows x 64 dims per warp) as fp16 pairs
    uint32_t qf[4][4];
    {
        const float* qp  = Q + (qrow_base + m0 + g) * DD + hoff;
        const float* qp8 = qp + 8 * DD;
        #pragma unroll
        for (int kc = 0; kc < 4; kc++) {
            int d = kc * 16 + 2 * j;
            qf[kc][0] = pack2(qp[d],      qp[d + 1]);
            qf[kc][1] = pack2(qp8[d],     qp8[d + 1]);
            qf[kc][2] = pack2(qp[d + 8],  qp[d + 9]);
            qf[kc][3] = pack2(qp8[d + 8], qp8[d + 9]);
        }
    }

    float out[8][4];
    #pragma unroll
    for (int nt = 0; nt < 8; nt++)
        #pragma unroll
        for (int i = 0; i < 4; i++) out[nt][i] = 0.0f;
    float mprev0 = -1e30f, mprev1 = -1e30f, l0 = 0.0f, l1 = 0.0f;

    const int ldr  = tid >> 4;        // 0..15  (K loader row)
    const int ldc4 = (tid & 15) * 4;  // 0..60
    const int vd   = tid & 63;        // V-transpose: d index
    const int vkp0 = tid >> 6;        // 0..3

    for (int kt = 0; kt < SS; kt += 64) {
        __syncthreads();
        const float* kp = K + (kv_base + kt) * DD + hoff;
        const float* vp = V + (kv_base + kt) * DD + hoff;
        // K: row-major half
        #pragma unroll
        for (int p = 0; p < 4; p++) {
            int row = ldr + p * 16;
            float4 kv = *(const float4*)&kp[(size_t)row * DD + ldc4];
            uint2 hk = make_uint2(pack2(kv.x, kv.y), pack2(kv.z, kv.w));
            *(uint2*)(Ks + row * KST + ldc4) = hk;
        }
        // V: transposed kv-pair half2, skewed
        #pragma unroll
        for (int it = 0; it < 8; it++) {
            int kpair = vkp0 + it * 4;              // 0..31
            float v0 = vp[(size_t)(2 * kpair)     * DD + vd];
            float v1 = vp[(size_t)(2 * kpair + 1) * DD + vd];
            int col = (kpair + (vd >> 3)) & 31;
            *(uint32_t*)(Vt + vd * KST + 2 * col) = pack2(v0, v1);
        }
        __syncthreads();

        // S = Q @ K^T  (16 x 64 per warp)
        float s[8][4];
        #pragma unroll
        for (int nt = 0; nt < 8; nt++)
            #pragma unroll
            for (int i = 0; i < 4; i++) s[nt][i] = 0.0f;

        #pragma unroll
        for (int kc = 0; kc < 4; kc++) {
            #pragma unroll
            for (int nt = 0; nt < 8; nt++) {
                const __half* kr = Ks + (nt * 8 + g) * KST + kc * 16 + 2 * j;
                uint32_t b0 = *(const uint32_t*)kr;
                uint32_t b1 = *(const uint32_t*)(kr + 8);
                mma_f16(s[nt][0], s[nt][1], s[nt][2], s[nt][3],
                        qf[kc][0], qf[kc][1], qf[kc][2], qf[kc][3], b0, b1);
            }
        }

        // Online softmax (rows g and g+8 of the warp slab)
        float mx0 = -1e30f, mx1 = -1e30f;
        #pragma unroll
        for (int nt = 0; nt < 8; nt++) {
            s[nt][0] *= 0.125f; s[nt][1] *= 0.125f;
            s[nt][2] *= 0.125f; s[nt][3] *= 0.125f;
            mx0 = fmaxf(mx0, fmaxf(s[nt][0], s[nt][1]));
            mx1 = fmaxf(mx1, fmaxf(s[nt][2], s[nt][3]));
        }
        mx0 = fmaxf(mx0, __shfl_xor_sync(0xffffffffu, mx0, 1));
        mx0 = fmaxf(mx0, __shfl_xor_sync(0xffffffffu, mx0, 2));
        mx1 = fmaxf(mx1, __shfl_xor_sync(0xffffffffu, mx1, 1));
        mx1 = fmaxf(mx1, __shfl_xor_sync(0xffffffffu, mx1, 2));

        float mn0 = fmaxf(mprev0, mx0);
        float mn1 = fmaxf(mprev1, mx1);
        float corr0 = __expf(mprev0 - mn0);
        float corr1 = __expf(mprev1 - mn1);
        mprev0 = mn0; mprev1 = mn1;

        float sum0 = 0.0f, sum1 = 0.0f;
        #pragma unroll
        for (int nt = 0; nt < 8; nt++) {
            s[nt][0] = __expf(s[nt][0] - mn0);
            s[nt][1] = __expf(s[nt][1] - mn0);
            s[nt][2] = __expf(s[nt][2] - mn1);
            s[nt][3] = __expf(s[nt][3] - mn1);
            sum0 += s[nt][0] + s[nt][1];
            sum1 += s[nt][2] + s[nt][3];
        }
        sum0 += __shfl_xor_sync(0xffffffffu, sum0, 1);
        sum0 += __shfl_xor_sync(0xffffffffu, sum0, 2);
        sum1 += __shfl_xor_sync(0xffffffffu, sum1, 1);
        sum1 += __shfl_xor_sync(0xffffffffu, sum1, 2);
        l0 = l0 * corr0 + sum0;
        l1 = l1 * corr1 + sum1;

        #pragma unroll
        for (int nt = 0; nt < 8; nt++) {
            out[nt][0] *= corr0; out[nt][1] *= corr0;
            out[nt][2] *= corr1; out[nt][3] *= corr1;
        }

        // out += P @ V : P A-fragments packed straight from S C-fragments
        #pragma unroll
        for (int kc = 0; kc < 4; kc++) {
            uint32_t a0 = pack2(s[2 * kc][0],     s[2 * kc][1]);
            uint32_t a1 = pack2(s[2 * kc][2],     s[2 * kc][3]);
            uint32_t a2 = pack2(s[2 * kc + 1][0], s[2 * kc + 1][1]);
            uint32_t a3 = pack2(s[2 * kc + 1][2], s[2 * kc + 1][3]);
            #pragma unroll
            for (int nt = 0; nt < 8; nt++) {
                const __half* vr = Vt + (nt * 8 + g) * KST;
                int c0 = (8 * kc + j     + nt) & 31;   // skew: (d>>3) = nt
                int c1 = (8 * kc + j + 4 + nt) & 31;
                uint32_t b0 = *(const uint32_t*)(vr + 2 * c0);
                uint32_t b1 = *(const uint32_t*)(vr + 2 * c1);
                mma_f16(out[nt][0], out[nt][1], out[nt][2], out[nt][3],
                        a0, a1, a2, a3, b0, b1);
            }
        }
    }

    // Epilogue: normalize, store ctx [B,S,D]
    float inv0 = 1.0f / l0;
    float inv1 = 1.0f / l1;
    float* op0 = O + (qrow_base + m0 + g) * DD + hoff + 2 * j;
    float* op1 = O + (qrow_base + m0 + g + 8) * DD + hoff + 2 * j;
    #pragma unroll
    for (int nt = 0; nt < 8; nt++) {
        float2 o0 = {out[nt][0] * inv0, out[nt][1] * inv0};
        float2 o1 = {out[nt][2] * inv1, out[nt][3] * inv1};
        *(float2*)&op0[nt * 8] = o0;
        *(float2*)&op1[nt * 8] = o1;
    }
}

// ---------------------------------------------------------------------------
// Launch
// ---------------------------------------------------------------------------
extern "C" void kernel_launch(void* const* d_in, const int* in_sizes, int n_in,
                              void* d_out, int out_size)
{
    const float* x  = (const float*)d_in[0];
    const float* wq = (const float*)d_in[1];
    const float* bq = (const float*)d_in[2];
    const float* wk = (const float*)d_in[3];
    const float* bk = (const float*)d_in[4];
    const float* wv = (const float*)d_in[5];
    const float* bv = (const float*)d_in[6];
    const float* wo = (const float*)d_in[7];
    const float* bo = (const float*)d_in[8];
    float* out = (float*)d_out;

    float *q, *k, *v, *ctx;
    cudaGetSymbolAddress((void**)&q,   g_q);
    cudaGetSymbolAddress((void**)&k,   g_k);
    cudaGetSymbolAddress((void**)&v,   g_v);
    cudaGetSymbolAddress((void**)&ctx, g_ctx);

    dim3 gemm_grid(DD / 128, MM / 128);   // (8, 64)

    gemm_tc_kernel<<<gemm_grid, 256>>>(x, wq, bq, q, MM, DD, DD);
    gemm_tc_kernel<<<gemm_grid, 256>>>(x, wk, bk, k, MM, DD, DD);
    gemm_tc_kernel<<<gemm_grid, 256>>>(x, wv, bv, v, MM, DD, DD);

    dim3 fa_grid(SS / 128, BB * HH);      // (16, 64)
    flash_tc_kernel<<<fa_grid, 256>>>(q, k, v, ctx);

    gemm_tc_kernel<<<gemm_grid, 256>>>(ctx, wo, bo, out, MM, DD, DD);
}

// round 12
// speedup vs baseline: 6.2232x; 1.1202x over previous
#include <cuda_runtime.h>
#include <cuda_fp16.h>
#include <stdint.h>
#include <math.h>

// Problem constants
#define BB  4
#define SS  2048
#define DD  1024
#define HH  16
#define DKK 64
#define MM  (BB * SS)          // 8192 rows

// ---------------------------------------------------------------------------
// Scratch (no allocations allowed -> __device__ globals), all fp16 now
// ---------------------------------------------------------------------------
__device__ __half g_q[MM * DD];
__device__ __half g_k[MM * DD];
__device__ __half g_v[MM * DD];
__device__ __half g_ctx[MM * DD];

// ---------------------------------------------------------------------------
// helpers
// ---------------------------------------------------------------------------
__device__ __forceinline__ uint32_t pack2(float lo, float hi) {
    __half2 h = __floats2half2_rn(lo, hi);
    return *reinterpret_cast<uint32_t*>(&h);
}

__device__ __forceinline__ void mma_f16(
    float& c0, float& c1, float& c2, float& c3,
    uint32_t a0, uint32_t a1, uint32_t a2, uint32_t a3,
    uint32_t b0, uint32_t b1)
{
    asm volatile(
        "mma.sync.aligned.m16n8k16.row.col.f32.f16.f16.f32 "
        "{%0,%1,%2,%3}, {%4,%5,%6,%7}, {%8,%9}, {%0,%1,%2,%3};"
        : "+f"(c0), "+f"(c1), "+f"(c2), "+f"(c3)
        : "r"(a0), "r"(a1), "r"(a2), "r"(a3), "r"(b0), "r"(b1));
}

__device__ __forceinline__ void ldmatrix_x4(
    uint32_t& r0, uint32_t& r1, uint32_t& r2, uint32_t& r3, const void* p)
{
    uint32_t a = (uint32_t)__cvta_generic_to_shared(p);
    asm volatile("ldmatrix.sync.aligned.m8n8.x4.shared.b16 {%0,%1,%2,%3}, [%4];"
                 : "=r"(r0), "=r"(r1), "=r"(r2), "=r"(r3) : "r"(a));
}

__device__ __forceinline__ void ldmatrix_x4_trans(
    uint32_t& r0, uint32_t& r1, uint32_t& r2, uint32_t& r3, const void* p)
{
    uint32_t a = (uint32_t)__cvta_generic_to_shared(p);
    asm volatile("ldmatrix.sync.aligned.m8n8.x4.trans.shared.b16 {%0,%1,%2,%3}, [%4];"
                 : "=r"(r0), "=r"(r1), "=r"(r2), "=r"(r3) : "r"(a));
}

__device__ __forceinline__ void cp16(void* smem_dst, const void* gsrc) {
    uint32_t sa = (uint32_t)__cvta_generic_to_shared(smem_dst);
    asm volatile("cp.async.cg.shared.global [%0], [%1], 16;" :: "r"(sa), "l"(gsrc));
}

// ---------------------------------------------------------------------------
// fp16 tensor-core GEMM + bias. Block 128x128, K-tile 32, 8 warps, 64x32/warp.
// A fragments via ldmatrix.x4. gridDim.z selects (B, bias, C) triple (QKV fuse).
// As: half [128][40] row-major (ldmatrix rows stride 20 words: banks 20i%32 CF)
// Bs: uint32(half2) [16][132]: word(kp,n) = {B[2kp][n], B[2kp+1][n]}
// ---------------------------------------------------------------------------
#define GA_STRIDE 40    // halfs
#define GB_STRIDE 132   // half2 words

template<bool AHALF, bool CHALF>
__global__ __launch_bounds__(256) void gemm_tc_kernel(
    const void* __restrict__ Ap,
    const float* __restrict__ B0, const float* __restrict__ B1, const float* __restrict__ B2,
    const float* __restrict__ bias0, const float* __restrict__ bias1, const float* __restrict__ bias2,
    void* __restrict__ C0, void* __restrict__ C1, void* __restrict__ C2,
    int M, int N, int K)
{
    const int z = blockIdx.z;
    const float* B    = z == 0 ? B0    : (z == 1 ? B1    : B2);
    const float* bias = z == 0 ? bias0 : (z == 1 ? bias1 : bias2);
    void* C           = z == 0 ? C0    : (z == 1 ? C1    : C2);

    __shared__ __align__(16) __half   As[128 * GA_STRIDE];
    __shared__ __align__(16) uint32_t Bs[16 * GB_STRIDE];

    const int tid  = threadIdx.x;
    const int lane = tid & 31;
    const int wid  = tid >> 5;
    const int g    = lane >> 2;
    const int j    = lane & 3;
    const int lrow8 = lane & 7;
    const int lm1   = (lane >> 3) & 1;
    const int lm2   = (lane >> 4) & 1;

    const int m0 = (wid & 1) * 64;
    const int n0 = (wid >> 1) * 32;
    const int row0 = blockIdx.y * 128;
    const int col0 = blockIdx.x * 128;

    // loaders: A: row=tid>>2 (+p*64), 8 k-elems at (tid&3)*8 ; B as before
    const int ar  = tid >> 2;
    const int ak  = (tid & 3) * 8;
    const int bkp = tid >> 5;
    const int bn0 = (tid & 31) * 4;

    float acc[4][4][4];
    #pragma unroll
    for (int mt = 0; mt < 4; mt++)
        #pragma unroll
        for (int nt = 0; nt < 4; nt++)
            #pragma unroll
            for (int i = 0; i < 4; i++) acc[mt][nt][i] = 0.0f;

    uint4  avh[2];
    float4 avf[2][2];
    float4 bv0[2], bv1[2];

    // prologue loads (k0 = 0)
    #pragma unroll
    for (int p = 0; p < 2; p++) {
        if (AHALF) {
            const __half* Ah = (const __half*)Ap;
            avh[p] = *(const uint4*)&Ah[(size_t)(row0 + ar + p * 64) * K + ak];
        } else {
            const float* Af = (const float*)Ap;
            avf[p][0] = *(const float4*)&Af[(size_t)(row0 + ar + p * 64) * K + ak];
            avf[p][1] = *(const float4*)&Af[(size_t)(row0 + ar + p * 64) * K + ak + 4];
        }
        int kp = bkp + p * 8;
        bv0[p] = *(const float4*)&B[(size_t)(2 * kp)     * N + col0 + bn0];
        bv1[p] = *(const float4*)&B[(size_t)(2 * kp + 1) * N + col0 + bn0];
    }

    for (int k0 = 0; k0 < K; k0 += 32) {
        __syncthreads();
        #pragma unroll
        for (int p = 0; p < 2; p++) {
            if (AHALF) {
                *(uint4*)(As + (ar + p * 64) * GA_STRIDE + ak) = avh[p];
            } else {
                uint4 h = make_uint4(pack2(avf[p][0].x, avf[p][0].y),
                                     pack2(avf[p][0].z, avf[p][0].w),
                                     pack2(avf[p][1].x, avf[p][1].y),
                                     pack2(avf[p][1].z, avf[p][1].w));
                *(uint4*)(As + (ar + p * 64) * GA_STRIDE + ak) = h;
            }
            int kp = bkp + p * 8;
            uint4 hb = make_uint4(pack2(bv0[p].x, bv1[p].x), pack2(bv0[p].y, bv1[p].y),
                                  pack2(bv0[p].z, bv1[p].z), pack2(bv0[p].w, bv1[p].w));
            *(uint4*)(Bs + kp * GB_STRIDE + bn0) = hb;
        }
        __syncthreads();

        // prefetch next k-tile
        if (k0 + 32 < K) {
            const int kn = k0 + 32;
            #pragma unroll
            for (int p = 0; p < 2; p++) {
                if (AHALF) {
                    const __half* Ah = (const __half*)Ap;
                    avh[p] = *(const uint4*)&Ah[(size_t)(row0 + ar + p * 64) * K + kn + ak];
                } else {
                    const float* Af = (const float*)Ap;
                    avf[p][0] = *(const float4*)&Af[(size_t)(row0 + ar + p * 64) * K + kn + ak];
                    avf[p][1] = *(const float4*)&Af[(size_t)(row0 + ar + p * 64) * K + kn + ak + 4];
                }
                int kp = bkp + p * 8;
                bv0[p] = *(const float4*)&B[(size_t)(kn + 2 * kp)     * N + col0 + bn0];
                bv1[p] = *(const float4*)&B[(size_t)(kn + 2 * kp + 1) * N + col0 + bn0];
            }
        }

        #pragma unroll
        for (int kc = 0; kc < 2; kc++) {
            uint32_t af[4][4], bf[4][2];
            #pragma unroll
            for (int mt = 0; mt < 4; mt++) {
                const __half* ap = As + (m0 + mt * 16 + lm1 * 8 + lrow8) * GA_STRIDE
                                      + kc * 16 + lm2 * 8;
                ldmatrix_x4(af[mt][0], af[mt][1], af[mt][2], af[mt][3], ap);
            }
            #pragma unroll
            for (int nt = 0; nt < 4; nt++) {
                int c = n0 + nt * 8 + g;
                bf[nt][0] = Bs[(8 * kc + j)     * GB_STRIDE + c];
                bf[nt][1] = Bs[(8 * kc + j + 4) * GB_STRIDE + c];
            }
            #pragma unroll
            for (int mt = 0; mt < 4; mt++)
                #pragma unroll
                for (int nt = 0; nt < 4; nt++)
                    mma_f16(acc[mt][nt][0], acc[mt][nt][1],
                            acc[mt][nt][2], acc[mt][nt][3],
                            af[mt][0], af[mt][1], af[mt][2], af[mt][3],
                            bf[nt][0], bf[nt][1]);
        }
    }

    // Epilogue with bias
    #pragma unroll
    for (int mt = 0; mt < 4; mt++) {
        int r = row0 + m0 + mt * 16 + g;
        #pragma unroll
        for (int nt = 0; nt < 4; nt++) {
            int c = col0 + n0 + nt * 8 + 2 * j;
            float b0 = bias[c], b1 = bias[c + 1];
            if (CHALF) {
                __half* Ch = (__half*)C;
                *(uint32_t*)&Ch[(size_t)r * N + c] =
                    pack2(acc[mt][nt][0] + b0, acc[mt][nt][1] + b1);
                *(uint32_t*)&Ch[(size_t)(r + 8) * N + c] =
                    pack2(acc[mt][nt][2] + b0, acc[mt][nt][3] + b1);
            } else {
                float* Cf = (float*)C;
                float2 o0 = {acc[mt][nt][0] + b0, acc[mt][nt][1] + b1};
                float2 o1 = {acc[mt][nt][2] + b0, acc[mt][nt][3] + b1};
                *(float2*)&Cf[(size_t)r * N + c]       = o0;
                *(float2*)&Cf[(size_t)(r + 8) * N + c] = o1;
            }
        }
    }
}

// ---------------------------------------------------------------------------
// Flash attention, fp16 in/out, fp32 softmax/accum.
// Q-tile 128, KV-tile 64. cp.async double-buffered K/V (row-major half,
// stride 72: ldmatrix row banks 36i%32 = 4i -> conflict-free).
// S-loop B-frags: ldmatrix.x4 on K. PV B-frags: ldmatrix.x4.trans on V.
// P never in SMEM (A-frags packed from S C-frags).
// ---------------------------------------------------------------------------
#define KST 72   // halfs per row
#define NT_TILES 32

__global__ __launch_bounds__(256) void flash_tc_kernel(
    const __half* __restrict__ Q, const __half* __restrict__ K,
    const __half* __restrict__ V, __half* __restrict__ O)
{
    __shared__ __align__(16) __half Ks[2][64 * KST];
    __shared__ __align__(16) __half Vs[2][64 * KST];

    const int tid  = threadIdx.x;
    const int lane = tid & 31;
    const int wid  = tid >> 5;
    const int g    = lane >> 2;
    const int j    = lane & 3;
    const int lrow8 = lane & 7;
    const int lm1   = (lane >> 3) & 1;
    const int lm2   = (lane >> 4) & 1;
    const int m0   = wid * 16;

    const int bh = blockIdx.y;
    const int b  = bh >> 4;
    const int h  = bh & 15;
    const int q0 = blockIdx.x * 128;

    const size_t qrow_base = (size_t)(b * SS + q0);
    const size_t kv_base   = (size_t)(b * SS);
    const int    hoff      = h * DKK;

    // Q fragments: direct uint32 loads from half (no conversion)
    uint32_t qf[4][4];
    {
        const __half* qp  = Q + (qrow_base + m0 + g) * DD + hoff;
        const __half* qp8 = qp + 8 * DD;
        #pragma unroll
        for (int kc = 0; kc < 4; kc++) {
            int d = kc * 16 + 2 * j;
            qf[kc][0] = *(const uint32_t*)(qp  + d);
            qf[kc][1] = *(const uint32_t*)(qp8 + d);
            qf[kc][2] = *(const uint32_t*)(qp  + d + 8);
            qf[kc][3] = *(const uint32_t*)(qp8 + d + 8);
        }
    }

    float out[8][4];
    #pragma unroll
    for (int nt = 0; nt < 8; nt++)
        #pragma unroll
        for (int i = 0; i < 4; i++) out[nt][i] = 0.0f;
    float mprev0 = -1e30f, mprev1 = -1e30f, l0 = 0.0f, l1 = 0.0f;

    // cp.async chunks: 512 x 16B per tile per array; 2 chunks/thread each
    const int c0r = tid >> 3;            // 0..31
    const int c0c = (tid & 7) * 8;       // half offset
    const int c1r = c0r + 32;

    const __half* kbase = K + kv_base * DD + hoff;
    const __half* vbase = V + kv_base * DD + hoff;

    // prologue: tile 0 -> stage 0
    {
        cp16(&Ks[0][c0r * KST + c0c], kbase + (size_t)c0r * DD + c0c);
        cp16(&Ks[0][c1r * KST + c0c], kbase + (size_t)c1r * DD + c0c);
        cp16(&Vs[0][c0r * KST + c0c], vbase + (size_t)c0r * DD + c0c);
        cp16(&Vs[0][c1r * KST + c0c], vbase + (size_t)c1r * DD + c0c);
        asm volatile("cp.async.commit_group;" ::: "memory");
    }

    for (int t = 0; t < NT_TILES; t++) {
        const int s = t & 1;
        if (t + 1 < NT_TILES) {
            const __half* kb = kbase + (size_t)(t + 1) * 64 * DD;
            const __half* vb = vbase + (size_t)(t + 1) * 64 * DD;
            const int sn = s ^ 1;
            cp16(&Ks[sn][c0r * KST + c0c], kb + (size_t)c0r * DD + c0c);
            cp16(&Ks[sn][c1r * KST + c0c], kb + (size_t)c1r * DD + c0c);
            cp16(&Vs[sn][c0r * KST + c0c], vb + (size_t)c0r * DD + c0c);
            cp16(&Vs[sn][c1r * KST + c0c], vb + (size_t)c1r * DD + c0c);
            asm volatile("cp.async.commit_group;" ::: "memory");
            asm volatile("cp.async.wait_group 1;" ::: "memory");
        } else {
            asm volatile("cp.async.wait_group 0;" ::: "memory");
        }
        __syncthreads();

        // S = Q @ K^T (16 x 64 per warp), B-frags via ldmatrix.x4
        float sc[8][4];
        #pragma unroll
        for (int nt = 0; nt < 8; nt++)
            #pragma unroll
            for (int i = 0; i < 4; i++) sc[nt][i] = 0.0f;

        const __half* ksb = &Ks[s][(lm2 * 8 + lrow8) * KST + lm1 * 8];
        #pragma unroll
        for (int kc = 0; kc < 4; kc++) {
            #pragma unroll
            for (int ntp = 0; ntp < 4; ntp++) {
                uint32_t b0, b1, b2, b3;
                ldmatrix_x4(b0, b1, b2, b3, ksb + ntp * 16 * KST + kc * 16);
                mma_f16(sc[2 * ntp][0], sc[2 * ntp][1], sc[2 * ntp][2], sc[2 * ntp][3],
                        qf[kc][0], qf[kc][1], qf[kc][2], qf[kc][3], b0, b1);
                mma_f16(sc[2 * ntp + 1][0], sc[2 * ntp + 1][1], sc[2 * ntp + 1][2], sc[2 * ntp + 1][3],
                        qf[kc][0], qf[kc][1], qf[kc][2], qf[kc][3], b2, b3);
            }
        }

        // Online softmax (rows g, g+8)
        float mx0 = -1e30f, mx1 = -1e30f;
        #pragma unroll
        for (int nt = 0; nt < 8; nt++) {
            sc[nt][0] *= 0.125f; sc[nt][1] *= 0.125f;
            sc[nt][2] *= 0.125f; sc[nt][3] *= 0.125f;
            mx0 = fmaxf(mx0, fmaxf(sc[nt][0], sc[nt][1]));
            mx1 = fmaxf(mx1, fmaxf(sc[nt][2], sc[nt][3]));
        }
        mx0 = fmaxf(mx0, __shfl_xor_sync(0xffffffffu, mx0, 1));
        mx0 = fmaxf(mx0, __shfl_xor_sync(0xffffffffu, mx0, 2));
        mx1 = fmaxf(mx1, __shfl_xor_sync(0xffffffffu, mx1, 1));
        mx1 = fmaxf(mx1, __shfl_xor_sync(0xffffffffu, mx1, 2));

        float mn0 = fmaxf(mprev0, mx0);
        float mn1 = fmaxf(mprev1, mx1);
        float corr0 = __expf(mprev0 - mn0);
        float corr1 = __expf(mprev1 - mn1);
        mprev0 = mn0; mprev1 = mn1;

        float sum0 = 0.0f, sum1 = 0.0f;
        #pragma unroll
        for (int nt = 0; nt < 8; nt++) {
            sc[nt][0] = __expf(sc[nt][0] - mn0);
            sc[nt][1] = __expf(sc[nt][1] - mn0);
            sc[nt][2] = __expf(sc[nt][2] - mn1);
            sc[nt][3] = __expf(sc[nt][3] - mn1);
            sum0 += sc[nt][0] + sc[nt][1];
            sum1 += sc[nt][2] + sc[nt][3];
        }
        sum0 += __shfl_xor_sync(0xffffffffu, sum0, 1);
        sum0 += __shfl_xor_sync(0xffffffffu, sum0, 2);
        sum1 += __shfl_xor_sync(0xffffffffu, sum1, 1);
        sum1 += __shfl_xor_sync(0xffffffffu, sum1, 2);
        l0 = l0 * corr0 + sum0;
        l1 = l1 * corr1 + sum1;

        #pragma unroll
        for (int nt = 0; nt < 8; nt++) {
            out[nt][0] *= corr0; out[nt][1] *= corr0;
            out[nt][2] *= corr1; out[nt][3] *= corr1;
        }

        // out += P @ V : A-frags from S C-frags, B-frags via ldmatrix.trans
        const __half* vsb = &Vs[s][(lm1 * 8 + lrow8) * KST + lm2 * 8];
        #pragma unroll
        for (int kc = 0; kc < 4; kc++) {
            uint32_t a0 = pack2(sc[2 * kc][0],     sc[2 * kc][1]);
            uint32_t a1 = pack2(sc[2 * kc][2],     sc[2 * kc][3]);
            uint32_t a2 = pack2(sc[2 * kc + 1][0], sc[2 * kc + 1][1]);
            uint32_t a3 = pack2(sc[2 * kc + 1][2], sc[2 * kc + 1][3]);
            #pragma unroll
            for (int ntp = 0; ntp < 4; ntp++) {
                uint32_t b0, b1, b2, b3;
                ldmatrix_x4_trans(b0, b1, b2, b3, vsb + kc * 16 * KST + ntp * 16);
                mma_f16(out[2 * ntp][0], out[2 * ntp][1], out[2 * ntp][2], out[2 * ntp][3],
                        a0, a1, a2, a3, b0, b1);
                mma_f16(out[2 * ntp + 1][0], out[2 * ntp + 1][1], out[2 * ntp + 1][2], out[2 * ntp + 1][3],
                        a0, a1, a2, a3, b2, b3);
            }
        }
        __syncthreads();
    }

    // Epilogue: normalize, store half ctx
    float inv0 = 1.0f / l0;
    float inv1 = 1.0f / l1;
    __half* op0 = O + (qrow_base + m0 + g) * DD + hoff + 2 * j;
    __half* op1 = op0 + 8 * DD;
    #pragma unroll
    for (int nt = 0; nt < 8; nt++) {
        *(uint32_t*)(op0 + nt * 8) = pack2(out[nt][0] * inv0, out[nt][1] * inv0);
        *(uint32_t*)(op1 + nt * 8) = pack2(out[nt][2] * inv1, out[nt][3] * inv1);
    }
}

// ---------------------------------------------------------------------------
// Launch
// ---------------------------------------------------------------------------
extern "C" void kernel_launch(void* const* d_in, const int* in_sizes, int n_in,
                              void* d_out, int out_size)
{
    const float* x  = (const float*)d_in[0];
    const float* wq = (const float*)d_in[1];
    const float* bq = (const float*)d_in[2];
    const float* wk = (const float*)d_in[3];
    const float* bk = (const float*)d_in[4];
    const float* wv = (const float*)d_in[5];
    const float* bv = (const float*)d_in[6];
    const float* wo = (const float*)d_in[7];
    const float* bo = (const float*)d_in[8];
    float* out = (float*)d_out;

    __half *q, *k, *v, *ctx;
    cudaGetSymbolAddress((void**)&q,   g_q);
    cudaGetSymbolAddress((void**)&k,   g_k);
    cudaGetSymbolAddress((void**)&v,   g_v);
    cudaGetSymbolAddress((void**)&ctx, g_ctx);

    // Fused Q/K/V projections: one launch, gridDim.z selects weight/bias/dst
    dim3 qkv_grid(DD / 128, MM / 128, 3);
    gemm_tc_kernel<false, true><<<qkv_grid, 256>>>(
        x, wq, wk, wv, bq, bk, bv, q, k, v, MM, DD, DD);

    dim3 fa_grid(SS / 128, BB * HH);      // (16, 64)
    flash_tc_kernel<<<fa_grid, 256>>>(q, k, v, ctx);

    dim3 out_grid(DD / 128, MM / 128, 1);
    gemm_tc_kernel<true, false><<<out_grid, 256>>>(
        ctx, wo, wo, wo, bo, bo, bo, out, out, out, MM, DD, DD);
}

// round 14
// speedup vs baseline: 7.3485x; 1.1808x over previous
#include <cuda_runtime.h>
#include <cuda_fp16.h>
#include <stdint.h>
#include <math.h>

// Problem constants
#define BB  4
#define SS  2048
#define DD  1024
#define HH  16
#define DKK 64
#define MM  (BB * SS)          // 8192 rows
#define NW_ ((size_t)DD * DD)  // one weight matrix

// ---------------------------------------------------------------------------
// Scratch (no allocations allowed -> __device__ globals), all fp16
// ---------------------------------------------------------------------------
__device__ __half g_q[MM * DD];
__device__ __half g_k[MM * DD];
__device__ __half g_v[MM * DD];
__device__ __half g_ctx[MM * DD];
__device__ __half g_xh[MM * DD];
__device__ __half g_wh[4 * DD * DD];   // wq, wk, wv, wo

// ---------------------------------------------------------------------------
// helpers
// ---------------------------------------------------------------------------
__device__ __forceinline__ uint32_t pack2(float lo, float hi) {
    __half2 h = __floats2half2_rn(lo, hi);
    return *reinterpret_cast<uint32_t*>(&h);
}

__device__ __forceinline__ void mma_f16(
    float& c0, float& c1, float& c2, float& c3,
    uint32_t a0, uint32_t a1, uint32_t a2, uint32_t a3,
    uint32_t b0, uint32_t b1)
{
    asm volatile(
        "mma.sync.aligned.m16n8k16.row.col.f32.f16.f16.f32 "
        "{%0,%1,%2,%3}, {%4,%5,%6,%7}, {%8,%9}, {%0,%1,%2,%3};"
        : "+f"(c0), "+f"(c1), "+f"(c2), "+f"(c3)
        : "r"(a0), "r"(a1), "r"(a2), "r"(a3), "r"(b0), "r"(b1));
}

__device__ __forceinline__ void ldmatrix_x4(
    uint32_t& r0, uint32_t& r1, uint32_t& r2, uint32_t& r3, const void* p)
{
    uint32_t a = (uint32_t)__cvta_generic_to_shared(p);
    asm volatile("ldmatrix.sync.aligned.m8n8.x4.shared.b16 {%0,%1,%2,%3}, [%4];"
                 : "=r"(r0), "=r"(r1), "=r"(r2), "=r"(r3) : "r"(a));
}

__device__ __forceinline__ void ldmatrix_x4_trans(
    uint32_t& r0, uint32_t& r1, uint32_t& r2, uint32_t& r3, const void* p)
{
    uint32_t a = (uint32_t)__cvta_generic_to_shared(p);
    asm volatile("ldmatrix.sync.aligned.m8n8.x4.trans.shared.b16 {%0,%1,%2,%3}, [%4];"
                 : "=r"(r0), "=r"(r1), "=r"(r2), "=r"(r3) : "r"(a));
}

__device__ __forceinline__ void cp16(void* smem_dst, const void* gsrc) {
    uint32_t sa = (uint32_t)__cvta_generic_to_shared(smem_dst);
    asm volatile("cp.async.cg.shared.global [%0], [%1], 16;" :: "r"(sa), "l"(gsrc));
}

// ---------------------------------------------------------------------------
// One-shot fp32 -> fp16 conversion: x and the 4 weight matrices.
// 8 elems/thread. Segment 0 = x, segments 1..4 = wq,wk,wv,wo.
// ---------------------------------------------------------------------------
__global__ __launch_bounds__(256) void cvt_kernel(
    const float* __restrict__ x,
    const float* __restrict__ wq, const float* __restrict__ wk,
    const float* __restrict__ wv, const float* __restrict__ wo,
    __half* __restrict__ xh, __half* __restrict__ wh)
{
    size_t i = ((size_t)blockIdx.x * blockDim.x + threadIdx.x) * 8;
    const size_t NX = (size_t)MM * DD;
    const float* src;
    __half* dst;
    size_t off;
    if (i < NX) {
        src = x; dst = xh; off = i;
    } else {
        size_t r = i - NX;
        int w = (int)(r / NW_);
        off = r % NW_;
        src = (w == 0) ? wq : (w == 1) ? wk : (w == 2) ? wv : wo;
        dst = wh + (size_t)w * NW_;
    }
    float4 a = *(const float4*)(src + off);
    float4 b = *(const float4*)(src + off + 4);
    uint4 h = make_uint4(pack2(a.x, a.y), pack2(a.z, a.w),
                         pack2(b.x, b.y), pack2(b.z, b.w));
    *(uint4*)(dst + off) = h;
}

// ---------------------------------------------------------------------------
// All-fp16 tensor-core GEMM + bias: C = A[M,K] @ W[K,N] + bias.
// Block 128x128, K-tile 32, 8 warps (64x32/warp). cp.async double-buffered.
// As: half [128][40]  (row banks 20r%32: CF).  A-frags: ldmatrix.x4.
// Bs: half [32][136]  (row banks 68r%32=4r: CF). B-frags: ldmatrix.x4.trans.
// gridDim.z picks (W slab, bias, C) for fused QKV.
// ---------------------------------------------------------------------------
#define GAS 40    // As stride (halfs)
#define GBS 136   // Bs stride (halfs)

template<bool CHALF>
__global__ __launch_bounds__(256) void gemm_h_kernel(
    const __half* __restrict__ A, const __half* __restrict__ Wbase,
    const float* __restrict__ bias0, const float* __restrict__ bias1,
    const float* __restrict__ bias2,
    void* __restrict__ C0, void* __restrict__ C1, void* __restrict__ C2,
    int M, int N, int K)
{
    const int z = blockIdx.z;
    const __half* W   = Wbase + (size_t)z * NW_;
    const float* bias = z == 0 ? bias0 : (z == 1 ? bias1 : bias2);
    void* C           = z == 0 ? C0    : (z == 1 ? C1    : C2);

    __shared__ __align__(16) __half As[2][128 * GAS];
    __shared__ __align__(16) __half Bs[2][32 * GBS];

    const int tid  = threadIdx.x;
    const int lane = tid & 31;
    const int wid  = tid >> 5;
    const int g    = lane >> 2;
    const int j    = lane & 3;
    const int lrow8 = lane & 7;
    const int lm1   = (lane >> 3) & 1;
    const int lm2   = (lane >> 4) & 1;

    const int m0 = (wid & 1) * 64;
    const int n0 = (wid >> 1) * 32;
    const int row0 = blockIdx.y * 128;
    const int col0 = blockIdx.x * 128;

    // cp.async chunk indices (16B = 8 halfs per chunk)
    const int ac0_r = tid >> 2,        ac0_o = (tid & 3) * 8;
    const int ac1_r = (tid + 256) >> 2, ac1_o = ((tid + 256) & 3) * 8;
    const int bc0_r = tid >> 4,        bc0_o = (tid & 15) * 8;
    const int bc1_r = (tid + 256) >> 4, bc1_o = ((tid + 256) & 15) * 8;

    float acc[4][4][4];
    #pragma unroll
    for (int mt = 0; mt < 4; mt++)
        #pragma unroll
        for (int nt = 0; nt < 4; nt++)
            #pragma unroll
            for (int i = 0; i < 4; i++) acc[mt][nt][i] = 0.0f;

    const __half* Abase = A + (size_t)row0 * K;
    const __half* Wb    = W + col0;
    const int NTILES = K / 32;

    // prologue: k-tile 0 -> stage 0
    {
        cp16(&As[0][ac0_r * GAS + ac0_o], Abase + (size_t)ac0_r * K + ac0_o);
        cp16(&As[0][ac1_r * GAS + ac1_o], Abase + (size_t)ac1_r * K + ac1_o);
        cp16(&Bs[0][bc0_r * GBS + bc0_o], Wb + (size_t)bc0_r * N + bc0_o);
        cp16(&Bs[0][bc1_r * GBS + bc1_o], Wb + (size_t)bc1_r * N + bc1_o);
        asm volatile("cp.async.commit_group;" ::: "memory");
    }

    for (int t = 0; t < NTILES; t++) {
        const int s = t & 1;
        if (t + 1 < NTILES) {
            const int kn = (t + 1) * 32;
            const int sn = s ^ 1;
            cp16(&As[sn][ac0_r * GAS + ac0_o], Abase + (size_t)ac0_r * K + kn + ac0_o);
            cp16(&As[sn][ac1_r * GAS + ac1_o], Abase + (size_t)ac1_r * K + kn + ac1_o);
            cp16(&Bs[sn][bc0_r * GBS + bc0_o], Wb + (size_t)(kn + bc0_r) * N + bc0_o);
            cp16(&Bs[sn][bc1_r * GBS + bc1_o], Wb + (size_t)(kn + bc1_r) * N + bc1_o);
            asm volatile("cp.async.commit_group;" ::: "memory");
            asm volatile("cp.async.wait_group 1;" ::: "memory");
        } else {
            asm volatile("cp.async.wait_group 0;" ::: "memory");
        }
        __syncthreads();

        const __half* asb = &As[s][(m0 + lm1 * 8 + lrow8) * GAS + lm2 * 8];
        const __half* bsb = &Bs[s][(lm1 * 8 + lrow8) * GBS + n0 + lm2 * 8];

        #pragma unroll
        for (int kc = 0; kc < 2; kc++) {
            uint32_t af[4][4], bf[4][2];
            #pragma unroll
            for (int mt = 0; mt < 4; mt++)
                ldmatrix_x4(af[mt][0], af[mt][1], af[mt][2], af[mt][3],
                            asb + mt * 16 * GAS + kc * 16);
            #pragma unroll
            for (int np = 0; np < 2; np++)
                ldmatrix_x4_trans(bf[2 * np][0], bf[2 * np][1],
                                  bf[2 * np + 1][0], bf[2 * np + 1][1],
                                  bsb + kc * 16 * GBS + np * 16);
            #pragma unroll
            for (int mt = 0; mt < 4; mt++)
                #pragma unroll
                for (int nt = 0; nt < 4; nt++)
                    mma_f16(acc[mt][nt][0], acc[mt][nt][1],
                            acc[mt][nt][2], acc[mt][nt][3],
                            af[mt][0], af[mt][1], af[mt][2], af[mt][3],
                            bf[nt][0], bf[nt][1]);
        }
        __syncthreads();
    }

    // Epilogue with bias
    #pragma unroll
    for (int mt = 0; mt < 4; mt++) {
        int r = row0 + m0 + mt * 16 + g;
        #pragma unroll
        for (int nt = 0; nt < 4; nt++) {
            int c = col0 + n0 + nt * 8 + 2 * j;
            float b0 = bias[c], b1 = bias[c + 1];
            if (CHALF) {
                __half* Ch = (__half*)C;
                *(uint32_t*)&Ch[(size_t)r * N + c] =
                    pack2(acc[mt][nt][0] + b0, acc[mt][nt][1] + b1);
                *(uint32_t*)&Ch[(size_t)(r + 8) * N + c] =
                    pack2(acc[mt][nt][2] + b0, acc[mt][nt][3] + b1);
            } else {
                float* Cf = (float*)C;
                float2 o0 = {acc[mt][nt][0] + b0, acc[mt][nt][1] + b1};
                float2 o1 = {acc[mt][nt][2] + b0, acc[mt][nt][3] + b1};
                *(float2*)&Cf[(size_t)r * N + c]       = o0;
                *(float2*)&Cf[(size_t)(r + 8) * N + c] = o1;
            }
        }
    }
}

// ---------------------------------------------------------------------------
// Flash attention: fp16 in/out, fp32 softmax/accum.
// ---------------------------------------------------------------------------
#define KST 72   // halfs per row
#define NT_TILES 32

__global__ __launch_bounds__(256) void flash_tc_kernel(
    const __half* __restrict__ Q, const __half* __restrict__ K,
    const __half* __restrict__ V, __half* __restrict__ O)
{
    __shared__ __align__(16) __half Ks[2][64 * KST];
    __shared__ __align__(16) __half Vs[2][64 * KST];

    const int tid  = threadIdx.x;
    const int lane = tid & 31;
    const int wid  = tid >> 5;
    const int g    = lane >> 2;
    const int j    = lane & 3;
    const int lrow8 = lane & 7;
    const int lm1   = (lane >> 3) & 1;
    const int lm2   = (lane >> 4) & 1;
    const int m0   = wid * 16;

    const int bh = blockIdx.y;
    const int b  = bh >> 4;
    const int h  = bh & 15;
    const int q0 = blockIdx.x * 128;

    const size_t qrow_base = (size_t)(b * SS + q0);
    const size_t kv_base   = (size_t)(b * SS);
    const int    hoff      = h * DKK;

    uint32_t qf[4][4];
    {
        const __half* qp  = Q + (qrow_base + m0 + g) * DD + hoff;
        const __half* qp8 = qp + 8 * DD;
        #pragma unroll
        for (int kc = 0; kc < 4; kc++) {
            int d = kc * 16 + 2 * j;
            qf[kc][0] = *(const uint32_t*)(qp  + d);
            qf[kc][1] = *(const uint32_t*)(qp8 + d);
            qf[kc][2] = *(const uint32_t*)(qp  + d + 8);
            qf[kc][3] = *(const uint32_t*)(qp8 + d + 8);
        }
    }

    float out[8][4];
    #pragma unroll
    for (int nt = 0; nt < 8; nt++)
        #pragma unroll
        for (int i = 0; i < 4; i++) out[nt][i] = 0.0f;
    float mprev0 = -1e30f, mprev1 = -1e30f, l0 = 0.0f, l1 = 0.0f;

    const int c0r = tid >> 3;
    const int c0c = (tid & 7) * 8;
    const int c1r = c0r + 32;

    const __half* kbase = K + kv_base * DD + hoff;
    const __half* vbase = V + kv_base * DD + hoff;

    {
        cp16(&Ks[0][c0r * KST + c0c], kbase + (size_t)c0r * DD + c0c);
        cp16(&Ks[0][c1r * KST + c0c], kbase + (size_t)c1r * DD + c0c);
        cp16(&Vs[0][c0r * KST + c0c], vbase + (size_t)c0r * DD + c0c);
        cp16(&Vs[0][c1r * KST + c0c], vbase + (size_t)c1r * DD + c0c);
        asm volatile("cp.async.commit_group;" ::: "memory");
    }

    for (int t = 0; t < NT_TILES; t++) {
        const int s = t & 1;
        if (t + 1 < NT_TILES) {
            const __half* kb = kbase + (size_t)(t + 1) * 64 * DD;
            const __half* vb = vbase + (size_t)(t + 1) * 64 * DD;
            const int sn = s ^ 1;
            cp16(&Ks[sn][c0r * KST + c0c], kb + (size_t)c0r * DD + c0c);
            cp16(&Ks[sn][c1r * KST + c0c], kb + (size_t)c1r * DD + c0c);
            cp16(&Vs[sn][c0r * KST + c0c], vb + (size_t)c0r * DD + c0c);
            cp16(&Vs[sn][c1r * KST + c0c], vb + (size_t)c1r * DD + c0c);
            asm volatile("cp.async.commit_group;" ::: "memory");
            asm volatile("cp.async.wait_group 1;" ::: "memory");
        } else {
            asm volatile("cp.async.wait_group 0;" ::: "memory");
        }
        __syncthreads();

        float sc[8][4];
        #pragma unroll
        for (int nt = 0; nt < 8; nt++)
            #pragma unroll
            for (int i = 0; i < 4; i++) sc[nt][i] = 0.0f;

        const __half* ksb = &Ks[s][(lm2 * 8 + lrow8) * KST + lm1 * 8];
        #pragma unroll
        for (int kc = 0; kc < 4; kc++) {
            #pragma unroll
            for (int ntp = 0; ntp < 4; ntp++) {
                uint32_t b0, b1, b2, b3;
                ldmatrix_x4(b0, b1, b2, b3, ksb + ntp * 16 * KST + kc * 16);
                mma_f16(sc[2 * ntp][0], sc[2 * ntp][1], sc[2 * ntp][2], sc[2 * ntp][3],
                        qf[kc][0], qf[kc][1], qf[kc][2], qf[kc][3], b0, b1);
                mma_f16(sc[2 * ntp + 1][0], sc[2 * ntp + 1][1], sc[2 * ntp + 1][2], sc[2 * ntp + 1][3],
                        qf[kc][0], qf[kc][1], qf[kc][2], qf[kc][3], b2, b3);
            }
        }

        float mx0 = -1e30f, mx1 = -1e30f;
        #pragma unroll
        for (int nt = 0; nt < 8; nt++) {
            sc[nt][0] *= 0.125f; sc[nt][1] *= 0.125f;
            sc[nt][2] *= 0.125f; sc[nt][3] *= 0.125f;
            mx0 = fmaxf(mx0, fmaxf(sc[nt][0], sc[nt][1]));
            mx1 = fmaxf(mx1, fmaxf(sc[nt][2], sc[nt][3]));
        }
        mx0 = fmaxf(mx0, __shfl_xor_sync(0xffffffffu, mx0, 1));
        mx0 = fmaxf(mx0, __shfl_xor_sync(0xffffffffu, mx0, 2));
        mx1 = fmaxf(mx1, __shfl_xor_sync(0xffffffffu, mx1, 1));
        mx1 = fmaxf(mx1, __shfl_xor_sync(0xffffffffu, mx1, 2));

        float mn0 = fmaxf(mprev0, mx0);
        float mn1 = fmaxf(mprev1, mx1);
        float corr0 = __expf(mprev0 - mn0);
        float corr1 = __expf(mprev1 - mn1);
        mprev0 = mn0; mprev1 = mn1;

        float sum0 = 0.0f, sum1 = 0.0f;
        #pragma unroll
        for (int nt = 0; nt < 8; nt++) {
            sc[nt][0] = __expf(sc[nt][0] - mn0);
            sc[nt][1] = __expf(sc[nt][1] - mn0);
            sc[nt][2] = __expf(sc[nt][2] - mn1);
            sc[nt][3] = __expf(sc[nt][3] - mn1);
            sum0 += sc[nt][0] + sc[nt][1];
            sum1 += sc[nt][2] + sc[nt][3];
        }
        sum0 += __shfl_xor_sync(0xffffffffu, sum0, 1);
        sum0 += __shfl_xor_sync(0xffffffffu, sum0, 2);
        sum1 += __shfl_xor_sync(0xffffffffu, sum1, 1);
        sum1 += __shfl_xor_sync(0xffffffffu, sum1, 2);
        l0 = l0 * corr0 + sum0;
        l1 = l1 * corr1 + sum1;

        #pragma unroll
        for (int nt = 0; nt < 8; nt++) {
            out[nt][0] *= corr0; out[nt][1] *= corr0;
            out[nt][2] *= corr1; out[nt][3] *= corr1;
        }

        const __half* vsb = &Vs[s][(lm1 * 8 + lrow8) * KST + lm2 * 8];
        #pragma unroll
        for (int kc = 0; kc < 4; kc++) {
            uint32_t a0 = pack2(sc[2 * kc][0],     sc[2 * kc][1]);
            uint32_t a1 = pack2(sc[2 * kc][2],     sc[2 * kc][3]);
            uint32_t a2 = pack2(sc[2 * kc + 1][0], sc[2 * kc + 1][1]);
            uint32_t a3 = pack2(sc[2 * kc + 1][2], sc[2 * kc + 1][3]);
            #pragma unroll
            for (int ntp = 0; ntp < 4; ntp++) {
                uint32_t b0, b1, b2, b3;
                ldmatrix_x4_trans(b0, b1, b2, b3, vsb + kc * 16 * KST + ntp * 16);
                mma_f16(out[2 * ntp][0], out[2 * ntp][1], out[2 * ntp][2], out[2 * ntp][3],
                        a0, a1, a2, a3, b0, b1);
                mma_f16(out[2 * ntp + 1][0], out[2 * ntp + 1][1], out[2 * ntp + 1][2], out[2 * ntp + 1][3],
                        a0, a1, a2, a3, b2, b3);
            }
        }
        __syncthreads();
    }

    float inv0 = 1.0f / l0;
    float inv1 = 1.0f / l1;
    __half* op0 = O + (qrow_base + m0 + g) * DD + hoff + 2 * j;
    __half* op1 = op0 + 8 * DD;
    #pragma unroll
    for (int nt = 0; nt < 8; nt++) {
        *(uint32_t*)(op0 + nt * 8) = pack2(out[nt][0] * inv0, out[nt][1] * inv0);
        *(uint32_t*)(op1 + nt * 8) = pack2(out[nt][2] * inv1, out[nt][3] * inv1);
    }
}

// ---------------------------------------------------------------------------
// Launch
// ---------------------------------------------------------------------------
extern "C" void kernel_launch(void* const* d_in, const int* in_sizes, int n_in,
                              void* d_out, int out_size)
{
    const float* x  = (const float*)d_in[0];
    const float* wq = (const float*)d_in[1];
    const float* bq = (const float*)d_in[2];
    const float* wk = (const float*)d_in[3];
    const float* bk = (const float*)d_in[4];
    const float* wv = (const float*)d_in[5];
    const float* bv = (const float*)d_in[6];
    const float* wo = (const float*)d_in[7];
    const float* bo = (const float*)d_in[8];
    float* out = (float*)d_out;

    __half *q, *k, *v, *ctx, *xh, *wh;
    cudaGetSymbolAddress((void**)&q,   g_q);
    cudaGetSymbolAddress((void**)&k,   g_k);
    cudaGetSymbolAddress((void**)&v,   g_v);
    cudaGetSymbolAddress((void**)&ctx, g_ctx);
    cudaGetSymbolAddress((void**)&xh,  g_xh);
    cudaGetSymbolAddress((void**)&wh,  g_wh);

    // 1. Convert x + weights to fp16 once
    const size_t total = (size_t)MM * DD + 4 * NW_;
    cvt_kernel<<<(unsigned)(total / (256 * 8)), 256>>>(x, wq, wk, wv, wo, xh, wh);

    // 2. Fused Q/K/V projections (all-fp16 operands)
    dim3 qkv_grid(DD / 128, MM / 128, 3);
    gemm_h_kernel<true><<<qkv_grid, 256>>>(
        xh, wh, bq, bk, bv, q, k, v, MM, DD, DD);

    // 3. Flash attention
    dim3 fa_grid(SS / 128, BB * HH);
    flash_tc_kernel<<<fa_grid, 256>>>(q, k, v, ctx);

    // 4. Output projection (fp32 out)
    dim3 out_grid(DD / 128, MM / 128, 1);
    gemm_h_kernel<false><<<out_grid, 256>>>(
        ctx, wh + 3 * NW_, bo, bo, bo, out, out, out, MM, DD, DD);
}

// round 17
// speedup vs baseline: 7.7166x; 1.0501x over previous
#include <cuda_runtime.h>
#include <cuda_fp16.h>
#include <stdint.h>
#include <math.h>

// Problem constants
#define BB  4
#define SS  2048
#define DD  1024
#define HH  16
#define DKK 64
#define MM  (BB * SS)          // 8192 rows
#define NW_ ((size_t)DD * DD)  // one weight matrix

// ---------------------------------------------------------------------------
// Scratch (no allocations allowed -> __device__ globals), all fp16
// ---------------------------------------------------------------------------
__device__ __half g_q[MM * DD];
__device__ __half g_k[MM * DD];
__device__ __half g_v[MM * DD];
__device__ __half g_ctx[MM * DD];
__device__ __half g_xh[MM * DD];
__device__ __half g_wh[4 * DD * DD];   // wq(pre-scaled by 1/8), wk, wv, wo

// ---------------------------------------------------------------------------
// helpers
// ---------------------------------------------------------------------------
__device__ __forceinline__ uint32_t pack2(float lo, float hi) {
    __half2 h = __floats2half2_rn(lo, hi);
    return *reinterpret_cast<uint32_t*>(&h);
}

__device__ __forceinline__ void mma_f16(
    float& c0, float& c1, float& c2, float& c3,
    uint32_t a0, uint32_t a1, uint32_t a2, uint32_t a3,
    uint32_t b0, uint32_t b1)
{
    asm volatile(
        "mma.sync.aligned.m16n8k16.row.col.f32.f16.f16.f32 "
        "{%0,%1,%2,%3}, {%4,%5,%6,%7}, {%8,%9}, {%0,%1,%2,%3};"
        : "+f"(c0), "+f"(c1), "+f"(c2), "+f"(c3)
        : "r"(a0), "r"(a1), "r"(a2), "r"(a3), "r"(b0), "r"(b1));
}

__device__ __forceinline__ void ldmatrix_x4(
    uint32_t& r0, uint32_t& r1, uint32_t& r2, uint32_t& r3, const void* p)
{
    uint32_t a = (uint32_t)__cvta_generic_to_shared(p);
    asm volatile("ldmatrix.sync.aligned.m8n8.x4.shared.b16 {%0,%1,%2,%3}, [%4];"
                 : "=r"(r0), "=r"(r1), "=r"(r2), "=r"(r3) : "r"(a));
}

__device__ __forceinline__ void ldmatrix_x4_trans(
    uint32_t& r0, uint32_t& r1, uint32_t& r2, uint32_t& r3, const void* p)
{
    uint32_t a = (uint32_t)__cvta_generic_to_shared(p);
    asm volatile("ldmatrix.sync.aligned.m8n8.x4.trans.shared.b16 {%0,%1,%2,%3}, [%4];"
                 : "=r"(r0), "=r"(r1), "=r"(r2), "=r"(r3) : "r"(a));
}

__device__ __forceinline__ void cp16(void* smem_dst, const void* gsrc) {
    uint32_t sa = (uint32_t)__cvta_generic_to_shared(smem_dst);
    asm volatile("cp.async.cg.shared.global [%0], [%1], 16;" :: "r"(sa), "l"(gsrc));
}

// ---------------------------------------------------------------------------
// One-shot fp32 -> fp16 conversion. wq (w==0) pre-scaled by 0.125 (exact,
// power of two -> downstream S values bit-identical to scaling post-GEMM).
// ---------------------------------------------------------------------------
__global__ __launch_bounds__(256) void cvt_kernel(
    const float* __restrict__ x,
    const float* __restrict__ wq, const float* __restrict__ wk,
    const float* __restrict__ wv, const float* __restrict__ wo,
    __half* __restrict__ xh, __half* __restrict__ wh)
{
    size_t i = ((size_t)blockIdx.x * blockDim.x + threadIdx.x) * 8;
    const size_t NX = (size_t)MM * DD;
    const float* src;
    __half* dst;
    size_t off;
    float scale = 1.0f;
    if (i < NX) {
        src = x; dst = xh; off = i;
    } else {
        size_t r = i - NX;
        int w = (int)(r / NW_);
        off = r % NW_;
        src = (w == 0) ? wq : (w == 1) ? wk : (w == 2) ? wv : wo;
        dst = wh + (size_t)w * NW_;
        if (w == 0) scale = 0.125f;
    }
    float4 a = *(const float4*)(src + off);
    float4 b = *(const float4*)(src + off + 4);
    uint4 h = make_uint4(pack2(a.x * scale, a.y * scale), pack2(a.z * scale, a.w * scale),
                         pack2(b.x * scale, b.y * scale), pack2(b.z * scale, b.w * scale));
    *(uint4*)(dst + off) = h;
}

// ---------------------------------------------------------------------------
// All-fp16 GEMM + bias: C = A[M,K] @ W[K,N] + bias*bsc.
// Block 128x128, K-tile 64, 2-stage cp.async, dynamic SMEM (~70KB).
// As: half [128][72] (row banks 36r%32=4r: CF). A-frags ldmatrix.x4.
// Bs: half [64][136] (row banks 68r%32=4r: CF). B-frags ldmatrix.x4.trans.
// gridDim.z selects (W slab, bias, C); bias scale applies to z==0 only.
// ---------------------------------------------------------------------------
#define GAS 72    // As stride (halfs)
#define GBS 136   // Bs stride (halfs)
#define GA_TILE (128 * GAS)   // halfs per A stage
#define GB_TILE (64 * GBS)    // halfs per B stage
#define GEMM_SMEM ((2 * GA_TILE + 2 * GB_TILE) * 2)   // 71680 bytes

template<bool CHALF>
__global__ __launch_bounds__(256) void gemm_h_kernel(
    const __half* __restrict__ A, const __half* __restrict__ Wbase,
    const float* __restrict__ bias0, const float* __restrict__ bias1,
    const float* __restrict__ bias2, float bscale0,
    void* __restrict__ C0, void* __restrict__ C1, void* __restrict__ C2,
    int M, int N, int K)
{
    const int z = blockIdx.z;
    const __half* W   = Wbase + (size_t)z * NW_;
    const float* bias = z == 0 ? bias0 : (z == 1 ? bias1 : bias2);
    void* C           = z == 0 ? C0    : (z == 1 ? C1    : C2);
    const float bsc   = (z == 0) ? bscale0 : 1.0f;

    extern __shared__ __align__(16) __half smem[];
    __half* As = smem;                      // [2][GA_TILE]
    __half* Bs = smem + 2 * GA_TILE;        // [2][GB_TILE]

    const int tid  = threadIdx.x;
    const int lane = tid & 31;
    const int wid  = tid >> 5;
    const int g    = lane >> 2;
    const int j    = lane & 3;
    const int lrow8 = lane & 7;
    const int lm1   = (lane >> 3) & 1;
    const int lm2   = (lane >> 4) & 1;

    const int m0 = (wid & 1) * 64;
    const int n0 = (wid >> 1) * 32;
    const int row0 = blockIdx.y * 128;
    const int col0 = blockIdx.x * 128;

    float acc[4][4][4];
    #pragma unroll
    for (int mt = 0; mt < 4; mt++)
        #pragma unroll
        for (int nt = 0; nt < 4; nt++)
            #pragma unroll
            for (int i = 0; i < 4; i++) acc[mt][nt][i] = 0.0f;

    const __half* Abase = A + (size_t)row0 * K;
    const __half* Wb    = W + col0;
    const int NTILES = K / 64;

    // cp.async maps: A tile 128x64 halfs = 1024 chunks (row=c>>3, off=(c&7)*8)
    //                B tile 64x128 halfs = 1024 chunks (row=c>>4, off=(c&15)*8)
    // 4 chunks per thread per tile each.
    #define GEMM_LOAD(stage, ktile)                                              \
        do {                                                                     \
            const int kb = (ktile) * 64;                                         \
            __half* asd = As + (stage) * GA_TILE;                                \
            __half* bsd = Bs + (stage) * GB_TILE;                                \
            _Pragma("unroll")                                                    \
            for (int ci = 0; ci < 4; ci++) {                                     \
                int c = tid + ci * 256;                                          \
                int arr = c >> 3, aoo = (c & 7) * 8;                             \
                cp16(asd + arr * GAS + aoo, Abase + (size_t)arr * K + kb + aoo); \
                int brr = c >> 4, boo = (c & 15) * 8;                            \
                cp16(bsd + brr * GBS + boo, Wb + (size_t)(kb + brr) * N + boo);  \
            }                                                                    \
            asm volatile("cp.async.commit_group;" ::: "memory");                 \
        } while (0)

    GEMM_LOAD(0, 0);

    for (int t = 0; t < NTILES; t++) {
        const int s = t & 1;
        if (t + 1 < NTILES) {
            GEMM_LOAD(s ^ 1, t + 1);
            asm volatile("cp.async.wait_group 1;" ::: "memory");
        } else {
            asm volatile("cp.async.wait_group 0;" ::: "memory");
        }
        __syncthreads();

        const __half* asb = As + s * GA_TILE + (m0 + lm1 * 8 + lrow8) * GAS + lm2 * 8;
        const __half* bsb = Bs + s * GB_TILE + (lm1 * 8 + lrow8) * GBS + n0 + lm2 * 8;

        #pragma unroll
        for (int kc = 0; kc < 4; kc++) {
            uint32_t af[4][4], bf[4][2];
            #pragma unroll
            for (int mt = 0; mt < 4; mt++)
                ldmatrix_x4(af[mt][0], af[mt][1], af[mt][2], af[mt][3],
                            asb + mt * 16 * GAS + kc * 16);
            #pragma unroll
            for (int np = 0; np < 2; np++)
                ldmatrix_x4_trans(bf[2 * np][0], bf[2 * np][1],
                                  bf[2 * np + 1][0], bf[2 * np + 1][1],
                                  bsb + kc * 16 * GBS + np * 16);
            #pragma unroll
            for (int mt = 0; mt < 4; mt++)
                #pragma unroll
                for (int nt = 0; nt < 4; nt++)
                    mma_f16(acc[mt][nt][0], acc[mt][nt][1],
                            acc[mt][nt][2], acc[mt][nt][3],
                            af[mt][0], af[mt][1], af[mt][2], af[mt][3],
                            bf[nt][0], bf[nt][1]);
        }
        __syncthreads();
    }
    #undef GEMM_LOAD

    // Epilogue with bias
    #pragma unroll
    for (int mt = 0; mt < 4; mt++) {
        int r = row0 + m0 + mt * 16 + g;
        #pragma unroll
        for (int nt = 0; nt < 4; nt++) {
            int c = col0 + n0 + nt * 8 + 2 * j;
            float b0 = bias[c] * bsc, b1 = bias[c + 1] * bsc;
            if (CHALF) {
                __half* Ch = (__half*)C;
                *(uint32_t*)&Ch[(size_t)r * N + c] =
                    pack2(acc[mt][nt][0] + b0, acc[mt][nt][1] + b1);
                *(uint32_t*)&Ch[(size_t)(r + 8) * N + c] =
                    pack2(acc[mt][nt][2] + b0, acc[mt][nt][3] + b1);
            } else {
                float* Cf = (float*)C;
                float2 o0 = {acc[mt][nt][0] + b0, acc[mt][nt][1] + b1};
                float2 o1 = {acc[mt][nt][2] + b0, acc[mt][nt][3] + b1};
                *(float2*)&Cf[(size_t)r * N + c]       = o0;
                *(float2*)&Cf[(size_t)(r + 8) * N + c] = o1;
            }
        }
    }
}

// ---------------------------------------------------------------------------
// Flash attention: fp16 in/out, fp32 softmax/accum. Q pre-scaled by 1/8
// (folded into wq), so no scale multiply in the softmax.
// ---------------------------------------------------------------------------
#define KST 72   // halfs per row
#define NT_TILES 32

__global__ __launch_bounds__(256) void flash_tc_kernel(
    const __half* __restrict__ Q, const __half* __restrict__ K,
    const __half* __restrict__ V, __half* __restrict__ O)
{
    __shared__ __align__(16) __half Ks[2][64 * KST];
    __shared__ __align__(16) __half Vs[2][64 * KST];

    const int tid  = threadIdx.x;
    const int lane = tid & 31;
    const int wid  = tid >> 5;
    const int g    = lane >> 2;
    const int j    = lane & 3;
    const int lrow8 = lane & 7;
    const int lm1   = (lane >> 3) & 1;
    const int lm2   = (lane >> 4) & 1;
    const int m0   = wid * 16;

    const int bh = blockIdx.y;
    const int b  = bh >> 4;
    const int h  = bh & 15;
    const int q0 = blockIdx.x * 128;

    const size_t qrow_base = (size_t)(b * SS + q0);
    const size_t kv_base   = (size_t)(b * SS);
    const int    hoff      = h * DKK;

    uint32_t qf[4][4];
    {
        const __half* qp  = Q + (qrow_base + m0 + g) * DD + hoff;
        const __half* qp8 = qp + 8 * DD;
        #pragma unroll
        for (int kc = 0; kc < 4; kc++) {
            int d = kc * 16 + 2 * j;
            qf[kc][0] = *(const uint32_t*)(qp  + d);
            qf[kc][1] = *(const uint32_t*)(qp8 + d);
            qf[kc][2] = *(const uint32_t*)(qp  + d + 8);
            qf[kc][3] = *(const uint32_t*)(qp8 + d + 8);
        }
    }

    float out[8][4];
    #pragma unroll
    for (int nt = 0; nt < 8; nt++)
        #pragma unroll
        for (int i = 0; i < 4; i++) out[nt][i] = 0.0f;
    float mprev0 = -1e30f, mprev1 = -1e30f, l0 = 0.0f, l1 = 0.0f;

    const int c0r = tid >> 3;
    const int c0c = (tid & 7) * 8;
    const int c1r = c0r + 32;

    const __half* kbase = K + kv_base * DD + hoff;
    const __half* vbase = V + kv_base * DD + hoff;

    {
        cp16(&Ks[0][c0r * KST + c0c], kbase + (size_t)c0r * DD + c0c);
        cp16(&Ks[0][c1r * KST + c0c], kbase + (size_t)c1r * DD + c0c);
        cp16(&Vs[0][c0r * KST + c0c], vbase + (size_t)c0r * DD + c0c);
        cp16(&Vs[0][c1r * KST + c0c], vbase + (size_t)c1r * DD + c0c);
        asm volatile("cp.async.commit_group;" ::: "memory");
    }

    for (int t = 0; t < NT_TILES; t++) {
        const int s = t & 1;
        if (t + 1 < NT_TILES) {
            const __half* kb = kbase + (size_t)(t + 1) * 64 * DD;
            const __half* vb = vbase + (size_t)(t + 1) * 64 * DD;
            const int sn = s ^ 1;
            cp16(&Ks[sn][c0r * KST + c0c], kb + (size_t)c0r * DD + c0c);
            cp16(&Ks[sn][c1r * KST + c0c], kb + (size_t)c1r * DD + c0c);
            cp16(&Vs[sn][c0r * KST + c0c], vb + (size_t)c0r * DD + c0c);
            cp16(&Vs[sn][c1r * KST + c0c], vb + (size_t)c1r * DD + c0c);
            asm volatile("cp.async.commit_group;" ::: "memory");
            asm volatile("cp.async.wait_group 1;" ::: "memory");
        } else {
            asm volatile("cp.async.wait_group 0;" ::: "memory");
        }
        __syncthreads();

        float sc[8][4];
        #pragma unroll
        for (int nt = 0; nt < 8; nt++)
            #pragma unroll
            for (int i = 0; i < 4; i++) sc[nt][i] = 0.0f;

        const __half* ksb = &Ks[s][(lm2 * 8 + lrow8) * KST + lm1 * 8];
        #pragma unroll
        for (int kc = 0; kc < 4; kc++) {
            #pragma unroll
            for (int ntp = 0; ntp < 4; ntp++) {
                uint32_t b0, b1, b2, b3;
                ldmatrix_x4(b0, b1, b2, b3, ksb + ntp * 16 * KST + kc * 16);
                mma_f16(sc[2 * ntp][0], sc[2 * ntp][1], sc[2 * ntp][2], sc[2 * ntp][3],
                        qf[kc][0], qf[kc][1], qf[kc][2], qf[kc][3], b0, b1);
                mma_f16(sc[2 * ntp + 1][0], sc[2 * ntp + 1][1], sc[2 * ntp + 1][2], sc[2 * ntp + 1][3],
                        qf[kc][0], qf[kc][1], qf[kc][2], qf[kc][3], b2, b3);
            }
        }

        // Online softmax (Q already carries the 1/8 scale)
        float mx0 = -1e30f, mx1 = -1e30f;
        #pragma unroll
        for (int nt = 0; nt < 8; nt++) {
            mx0 = fmaxf(mx0, fmaxf(sc[nt][0], sc[nt][1]));
            mx1 = fmaxf(mx1, fmaxf(sc[nt][2], sc[nt][3]));
        }
        mx0 = fmaxf(mx0, __shfl_xor_sync(0xffffffffu, mx0, 1));
        mx0 = fmaxf(mx0, __shfl_xor_sync(0xffffffffu, mx0, 2));
        mx1 = fmaxf(mx1, __shfl_xor_sync(0xffffffffu, mx1, 1));
        mx1 = fmaxf(mx1, __shfl_xor_sync(0xffffffffu, mx1, 2));

        float mn0 = fmaxf(mprev0, mx0);
        float mn1 = fmaxf(mprev1, mx1);
        float corr0 = __expf(mprev0 - mn0);
        float corr1 = __expf(mprev1 - mn1);
        mprev0 = mn0; mprev1 = mn1;

        float sum0 = 0.0f, sum1 = 0.0f;
        #pragma unroll
        for (int nt = 0; nt < 8; nt++) {
            sc[nt][0] = __expf(sc[nt][0] - mn0);
            sc[nt][1] = __expf(sc[nt][1] - mn0);
            sc[nt][2] = __expf(sc[nt][2] - mn1);
            sc[nt][3] = __expf(sc[nt][3] - mn1);
            sum0 += sc[nt][0] + sc[nt][1];
            sum1 += sc[nt][2] + sc[nt][3];
        }
        sum0 += __shfl_xor_sync(0xffffffffu, sum0, 1);
        sum0 += __shfl_xor_sync(0xffffffffu, sum0, 2);
        sum1 += __shfl_xor_sync(0xffffffffu, sum1, 1);
        sum1 += __shfl_xor_sync(0xffffffffu, sum1, 2);
        l0 = l0 * corr0 + sum0;
        l1 = l1 * corr1 + sum1;

        #pragma unroll
        for (int nt = 0; nt < 8; nt++) {
            out[nt][0] *= corr0; out[nt][1] *= corr0;
            out[nt][2] *= corr1; out[nt][3] *= corr1;
        }

        const __half* vsb = &Vs[s][(lm1 * 8 + lrow8) * KST + lm2 * 8];
        #pragma unroll
        for (int kc = 0; kc < 4; kc++) {
            uint32_t a0 = pack2(sc[2 * kc][0],     sc[2 * kc][1]);
            uint32_t a1 = pack2(sc[2 * kc][2],     sc[2 * kc][3]);
            uint32_t a2 = pack2(sc[2 * kc + 1][0], sc[2 * kc + 1][1]);
            uint32_t a3 = pack2(sc[2 * kc + 1][2], sc[2 * kc + 1][3]);
            #pragma unroll
            for (int ntp = 0; ntp < 4; ntp++) {
                uint32_t b0, b1, b2, b3;
                ldmatrix_x4_trans(b0, b1, b2, b3, vsb + kc * 16 * KST + ntp * 16);
                mma_f16(out[2 * ntp][0], out[2 * ntp][1], out[2 * ntp][2], out[2 * ntp][3],
                        a0, a1, a2, a3, b0, b1);
                mma_f16(out[2 * ntp + 1][0], out[2 * ntp + 1][1], out[2 * ntp + 1][2], out[2 * ntp + 1][3],
                        a0, a1, a2, a3, b2, b3);
            }
        }
        __syncthreads();
    }

    float inv0 = 1.0f / l0;
    float inv1 = 1.0f / l1;
    __half* op0 = O + (qrow_base + m0 + g) * DD + hoff + 2 * j;
    __half* op1 = op0 + 8 * DD;
    #pragma unroll
    for (int nt = 0; nt < 8; nt++) {
        *(uint32_t*)(op0 + nt * 8) = pack2(out[nt][0] * inv0, out[nt][1] * inv0);
        *(uint32_t*)(op1 + nt * 8) = pack2(out[nt][2] * inv1, out[nt][3] * inv1);
    }
}

// ---------------------------------------------------------------------------
// Launch
// ---------------------------------------------------------------------------
extern "C" void kernel_launch(void* const* d_in, const int* in_sizes, int n_in,
                              void* d_out, int out_size)
{
    const float* x  = (const float*)d_in[0];
    const float* wq = (const float*)d_in[1];
    const float* bq = (const float*)d_in[2];
    const float* wk = (const float*)d_in[3];
    const float* bk = (const float*)d_in[4];
    const float* wv = (const float*)d_in[5];
    const float* bv = (const float*)d_in[6];
    const float* wo = (const float*)d_in[7];
    const float* bo = (const float*)d_in[8];
    float* out = (float*)d_out;

    __half *q, *k, *v, *ctx, *xh, *wh;
    cudaGetSymbolAddress((void**)&q,   g_q);
    cudaGetSymbolAddress((void**)&k,   g_k);
    cudaGetSymbolAddress((void**)&v,   g_v);
    cudaGetSymbolAddress((void**)&ctx, g_ctx);
    cudaGetSymbolAddress((void**)&xh,  g_xh);
    cudaGetSymbolAddress((void**)&wh,  g_wh);

    cudaFuncSetAttribute(gemm_h_kernel<true>,
                         cudaFuncAttributeMaxDynamicSharedMemorySize, GEMM_SMEM);
    cudaFuncSetAttribute(gemm_h_kernel<false>,
                         cudaFuncAttributeMaxDynamicSharedMemorySize, GEMM_SMEM);

    // 1. Convert x + weights to fp16 once (wq scaled by 1/8)
    const size_t total = (size_t)MM * DD + 4 * NW_;
    cvt_kernel<<<(unsigned)(total / (256 * 8)), 256>>>(x, wq, wk, wv, wo, xh, wh);

    // 2. Fused Q/K/V projections
    dim3 qkv_grid(DD / 128, MM / 128, 3);
    gemm_h_kernel<true><<<qkv_grid, 256, GEMM_SMEM>>>(
        xh, wh, bq, bk, bv, 0.125f, q, k, v, MM, DD, DD);

    // 3. Flash attention
    dim3 fa_grid(SS / 128, BB * HH);
    flash_tc_kernel<<<fa_grid, 256>>>(q, k, v, ctx);

    // 4. Output projection (fp32 out)
    dim3 out_grid(DD / 128, MM / 128, 1);
    gemm_h_kernel<false><<<out_grid, 256, GEMM_SMEM>>>(
        ctx, wh + 3 * NW_, bo, bo, bo, 1.0f, out, out, out, MM, DD, DD);
}